// round 11
// baseline (speedup 1.0000x reference)
#include <cuda_runtime.h>
#include <cuda_fp16.h>
#include <cstdint>
#include <math.h>

#define B_    2
#define S_    2048
#define H_    2048
#define HEADS 16
#define DH    128
#define BH    (B_*HEADS)
#define BSH   ((size_t)B_*S_*H_)
#define KT_A  64

// ---------------------------------------------------------------------------
__device__ __half g_qfr[BSH];                    // Q flash-A-frags fp16
__device__ __half g_kfr[BSH];                    // K flash-B-frags fp16
__device__ __half g_vfr[BSH];                    // V flash-B-frags fp16
__device__ __half g_lnp[BSH];                    // LN out, GEMM-A-frag fp16
__device__ __half g_ctxp[BSH];                   // ctx,    GEMM-A-frag fp16
__device__ __half g_qkvwP[(size_t)3*H_*H_];      // qkvw, B-frag fp16
__device__ __half g_owP[(size_t)H_*H_];          // ow,   B-frag fp16

// ---------------------------------------------------------------------------
__device__ __forceinline__ uint32_t h2u(__half2 h) { return *(uint32_t*)&h; }
__device__ __forceinline__ void mma_f16(float* c, const uint32_t* a, const uint32_t* b) {
    asm volatile(
        "mma.sync.aligned.m16n8k16.row.col.f32.f16.f16.f32 "
        "{%0,%1,%2,%3},{%4,%5,%6,%7},{%8,%9},{%0,%1,%2,%3};\n"
        : "+f"(c[0]), "+f"(c[1]), "+f"(c[2]), "+f"(c[3])
        : "r"(a[0]), "r"(a[1]), "r"(a[2]), "r"(a[3]), "r"(b[0]), "r"(b[1]));
}
__device__ __forceinline__ void cp16(uint32_t dst, const void* src) {
    asm volatile("cp.async.cg.shared.global [%0], [%1], 16;\n" :: "r"(dst), "l"(src));
}
#define CP_COMMIT() asm volatile("cp.async.commit_group;\n")
#define CP_WAIT0()  asm volatile("cp.async.wait_group 0;\n")
#define CP_WAIT1()  asm volatile("cp.async.wait_group 1;\n")

// fp16 GEMM A-fragment index (m16n8k16), K=2048
__device__ __forceinline__ size_t afragH(int m, int k) {
    return ((size_t)((m >> 4) * KT_A + (k >> 5))) * 512
         + (((k >> 4) & 1) * 256)
         + (((m & 7) * 4 + ((k >> 1) & 3)) * 8)
         + ((((k >> 3) & 1) * 2 + ((m >> 3) & 1)) * 2)
         + (k & 1);
}

// ---------------------------------------------------------------------------
// Weight prep: w[K][N] -> fp16 B-frag chunks [n32][kt]: 1024 halfs
// ---------------------------------------------------------------------------
__global__ void __launch_bounds__(256) prep_b(
    const float* __restrict__ w, __half* __restrict__ out, int N)
{
    const int kt = blockIdx.x, n32 = blockIdx.y;
    __shared__ float sm[32][33];
    const int tx = threadIdx.x;
    const int kl = tx >> 5, nl = tx & 31;
    #pragma unroll
    for (int i = 0; i < 32; i += 8)
        sm[kl + i][nl] = w[(size_t)(kt * 32 + kl + i) * N + n32 * 32 + nl];
    __syncthreads();
    const size_t base = ((size_t)n32 * KT_A + kt) * 1024;
    #pragma unroll
    for (int e = tx; e < 1024; e += 256) {
        const int k = e >> 5, n = e & 31;
        const int off = ((k >> 4) * 512) + (((k >> 3) & 1) * 256)
                      + (((n & 7) * 4 + ((k >> 1) & 3)) * 8)
                      + ((n >> 3) * 2) + (k & 1);
        out[base + off] = __float2half_rn(sm[k][n]);
    }
}

// ---------------------------------------------------------------------------
// LayerNorm: exact y + fp16 GEMM-A-frag copy
// ---------------------------------------------------------------------------
__global__ void __launch_bounds__(256) ln_kernel(
    const float* __restrict__ x, const float* __restrict__ g,
    const float* __restrict__ b, float* __restrict__ y, __half* __restrict__ yp)
{
    const int row = blockIdx.x;
    const float* xr = x + (size_t)row * H_;
    float s = 0.f, ss = 0.f;
    for (int i = threadIdx.x; i < H_; i += 256) {
        float t = xr[i];
        s += t; ss += t * t;
    }
    #pragma unroll
    for (int o = 16; o; o >>= 1) {
        s  += __shfl_xor_sync(0xffffffffu, s,  o);
        ss += __shfl_xor_sync(0xffffffffu, ss, o);
    }
    __shared__ float red[2][8];
    const int w = threadIdx.x >> 5, l = threadIdx.x & 31;
    if (l == 0) { red[0][w] = s; red[1][w] = ss; }
    __syncthreads();
    __shared__ float stats[2];
    if (threadIdx.x == 0) {
        float S = 0.f, SS = 0.f;
        #pragma unroll
        for (int i = 0; i < 8; i++) { S += red[0][i]; SS += red[1][i]; }
        float mu  = S / (float)H_;
        float var = SS / (float)H_ - mu * mu;
        stats[0] = mu;
        stats[1] = rsqrtf(var + 1e-12f);
    }
    __syncthreads();
    const float mu = stats[0], rstd = stats[1];
    float* yr = y + (size_t)row * H_;
    for (int i = threadIdx.x; i < H_; i += 256) {
        float v = (xr[i] - mu) * rstd * g[i] + b[i];
        yr[i] = v;
        yp[afragH(row, i)] = __float2half_rn(v);
    }
}

// ---------------------------------------------------------------------------
// FP16 mma.sync GEMM, CTA 128x256, 8 warps (2Mx4N), warp tile 64x64,
// K-tile 32, 3-stage cp.async pipeline, 1 CTA/SM.
// EPI: 0 plain C; 3 QKV scatter (flash frags + exact k/v + bias).
// ---------------------------------------------------------------------------
#define STG_HALFS 12288                   // A 4096 + B 8192 halfs = 24 KB
#define GEMM_SMEM (3 * STG_HALFS * 2)     // 73728 B

template<int EPI>
__global__ void __launch_bounds__(256, 1) mma_gemm2(
    const __half* __restrict__ Ap, const __half* __restrict__ Bp,
    float* __restrict__ C,
    __half* __restrict__ Qf, float* __restrict__ Ck, float* __restrict__ Cv,
    __half* __restrict__ Kf, __half* __restrict__ Vf,
    const float* __restrict__ bias, int Ntot)
{
    const int m16g0 = blockIdx.y * 8;
    const int n32g0 = blockIdx.x * 8;
    const int rowBase = blockIdx.y * 128;
    const int colBase = blockIdx.x * 256;

    extern __shared__ __half smh[];
    const uint32_t smemU = (uint32_t)__cvta_generic_to_shared(smh);

    const int tx = threadIdx.x;
    const int lane = tx & 31, warp = tx >> 5;
    const int wm = (warp >> 2) * 64;   // 0 or 64
    const int wn = (warp & 3) * 64;    // 0..192
    const int lr = lane >> 2;
    const int lc = lane & 3;

    auto loadStage = [&](int kt, int st) {
        const uint32_t sbase = smemU + st * STG_HALFS * 2;
        #pragma unroll
        for (int i = 0; i < 6; i++) {
            const int idx = tx + i * 256;          // uint4 index 0..1535
            if (idx < 512) {                        // A: 8 chunks x 64 uint4
                const int g = idx >> 6, rem = idx & 63;
                cp16(sbase + idx * 16,
                     Ap + ((size_t)(m16g0 + g) * KT_A + kt) * 512 + rem * 8);
            } else {                                // B: 8 chunks x 128 uint4
                const int j = idx - 512;
                const int nb = j >> 7, rem = j & 127;
                cp16(sbase + idx * 16,
                     Bp + ((size_t)(n32g0 + nb) * KT_A + kt) * 1024 + rem * 8);
            }
        }
    };

    float acc[4][8][4];
    #pragma unroll
    for (int i = 0; i < 4; i++)
        #pragma unroll
        for (int j = 0; j < 8; j++)
            #pragma unroll
            for (int r = 0; r < 4; r++) acc[i][j][r] = 0.f;

    loadStage(0, 0); CP_COMMIT();
    loadStage(1, 1); CP_COMMIT();

    for (int kt = 0; kt < KT_A; kt++) {
        const int st = kt % 3;
        CP_WAIT1();
        __syncthreads();
        if (kt + 2 < KT_A) { loadStage(kt + 2, (kt + 2) % 3); CP_COMMIT(); }

        const __half* sf = smh + st * STG_HALFS;
        const __half* aB = sf + (warp >> 2) * 2048;         // 4 m16-chunks
        const __half* bB = sf + 4096 + (warp & 3) * 2048;   // 2 n32-chunks

        #pragma unroll
        for (int ks = 0; ks < 2; ks++) {
            uint32_t af[4][4];
            #pragma unroll
            for (int mt = 0; mt < 4; mt++) {
                uint4 t = *(const uint4*)(aB + mt * 512 + ks * 256 + lane * 8);
                af[mt][0] = t.x; af[mt][1] = t.y; af[mt][2] = t.z; af[mt][3] = t.w;
            }
            uint32_t bf[8][2];
            #pragma unroll
            for (int nc = 0; nc < 2; nc++) {
                uint4 t0 = *(const uint4*)(bB + nc * 1024 + ks * 512 + lane * 8);
                uint4 t1 = *(const uint4*)(bB + nc * 1024 + ks * 512 + 256 + lane * 8);
                bf[nc * 4 + 0][0] = t0.x; bf[nc * 4 + 0][1] = t1.x;
                bf[nc * 4 + 1][0] = t0.y; bf[nc * 4 + 1][1] = t1.y;
                bf[nc * 4 + 2][0] = t0.z; bf[nc * 4 + 2][1] = t1.z;
                bf[nc * 4 + 3][0] = t0.w; bf[nc * 4 + 3][1] = t1.w;
            }
            #pragma unroll
            for (int mt = 0; mt < 4; mt++)
                #pragma unroll
                for (int nt = 0; nt < 8; nt++)
                    mma_f16(acc[mt][nt], af[mt], bf[nt]);
        }
    }

    if (EPI == 3) {
        const int whichBlk = colBase >> 11;   // 256-tiles never straddle q/k/v
        #pragma unroll
        for (int mt = 0; mt < 4; mt++) {
            #pragma unroll
            for (int nt = 0; nt < 8; nt++) {
                const int gn = colBase + wn + nt * 8 + 2 * lc;
                const int d  = gn & 127;
                const int h  = (gn & 2047) >> 7;
                const int m0 = rowBase + wm + mt * 16 + lr;
                const int b  = m0 >> 11, s = m0 & 2047;
                float* a = acc[mt][nt];
                const float v00 = a[0] + bias[gn], v01 = a[1] + bias[gn + 1];
                const float v10 = a[2] + bias[gn], v11 = a[3] + bias[gn + 1];
                if (whichBlk == 0) {
                    __half* qp = Qf
                        + (((((size_t)(b * 16 + h) * 16 + (s >> 7)) * 8 + ((s >> 4) & 7)) * 8
                            + (d >> 4)) * 256) + lane * 8 + ((d >> 3) & 1) * 4;
                    *(__half2*)(qp)     = __floats2half2_rn(v00, v01);
                    *(__half2*)(qp + 2) = __floats2half2_rn(v10, v11);
                } else {
                    float* base = (whichBlk == 1) ? Ck : Cv;
                    *(float2*)&base[((((size_t)b * 16 + h) << 11) + s) * 128 + d] =
                        make_float2(v00, v01);
                    *(float2*)&base[((((size_t)b * 16 + h) << 11) + s + 8) * 128 + d] =
                        make_float2(v10, v11);
                    if (whichBlk == 1) {
                        __half* kb = Kf + (((size_t)(b * 16 + h) * 32) + (s >> 6)) * 8192
                                   + (d >> 4) * 1024 + lane * 8 + ((d >> 3) & 1) * 2;
                        const int nt0 = (s & 63) >> 3;
                        *(__half2*)(kb + (nt0 >> 1) * 256 + (nt0 & 1) * 4) =
                            __floats2half2_rn(v00, v01);
                        const int nt1 = nt0 + 1;
                        *(__half2*)(kb + (nt1 >> 1) * 256 + (nt1 & 1) * 4) =
                            __floats2half2_rn(v10, v11);
                    } else {
                        const size_t vblk =
                            (((size_t)(b * 16 + h) * 32) + (s >> 6)) * 8192
                            + ((s & 63) >> 4) * 2048 + (d >> 4) * 256;
                        auto vst = [&](int ss, int dd, float val) {
                            const int la = (dd & 7) * 4 + ((ss >> 1) & 3);
                            Vf[vblk + la * 8 + ((dd >> 3) & 1) * 4
                               + ((ss & 15) >> 3) * 2 + (ss & 1)] = __float2half_rn(val);
                        };
                        vst(s, d, v00);     vst(s, d + 1, v01);
                        vst(s + 8, d, v10); vst(s + 8, d + 1, v11);
                    }
                }
            }
        }
        return;
    }

    #pragma unroll
    for (int mt = 0; mt < 4; mt++) {
        #pragma unroll
        for (int nt = 0; nt < 8; nt++) {
            const int gm = rowBase + wm + mt * 16 + lr;
            const int gn = colBase + wn + nt * 8 + 2 * lc;
            float* a = acc[mt][nt];
            #pragma unroll
            for (int r = 0; r < 2; r++)
                *(float2*)&C[(size_t)(gm + r * 8) * Ntot + gn] =
                    make_float2(a[r * 2 + 0], a[r * 2 + 1]);
        }
    }
}

// ---------------------------------------------------------------------------
// FP16 flash attention (unchanged from R10)
// ---------------------------------------------------------------------------
#define FLASH_SMEM (4 * 8192 * 2)

__global__ void __launch_bounds__(256, 1) flash_kernel(
    const __half* __restrict__ qf, const __half* __restrict__ kf,
    const __half* __restrict__ vf, const float* __restrict__ mask,
    float* __restrict__ ctx, __half* __restrict__ ctxp, float scale)
{
    const int qi = gridDim.x - 1 - blockIdx.x;
    const int rowBase = qi * 128;
    const int bh = blockIdx.y;
    const int b = bh >> 4, h = bh & 15;

    const __half* Kg = kf + (size_t)bh * 32 * 8192;
    const __half* Vg = vf + (size_t)bh * 32 * 8192;
    const float* mrow = mask + (size_t)b * S_;

    extern __shared__ __half smh[];
    const uint32_t smemU = (uint32_t)__cvta_generic_to_shared(smh);

    const int tx = threadIdx.x;
    const int lane = tx & 31, wid = tx >> 5;
    const int lr = lane >> 2, lc = lane & 3;
    const int r0g = rowBase + wid * 16 + lr;
    const int r1g = r0g + 8;

    uint32_t qfr[8][4];
    {
        const __half* Qg = qf + (((size_t)bh * 16 + qi) * 8 + wid) * 2048 + lane * 8;
        #pragma unroll
        for (int ks = 0; ks < 8; ks++) {
            uint4 t = *(const uint4*)(Qg + ks * 256);
            qfr[ks][0] = t.x; qfr[ks][1] = t.y; qfr[ks][2] = t.z; qfr[ks][3] = t.w;
        }
    }

    const int jEnd = 2 * qi + 2;
    auto cpKV = [&](int j, int st) {
        const __half* ksrc = Kg + (size_t)j * 8192;
        const __half* vsrc = Vg + (size_t)j * 8192;
        const uint32_t kd = smemU + st * 16384;
        const uint32_t vd = smemU + 32768 + st * 16384;
        #pragma unroll
        for (int i = 0; i < 4; i++) {
            const int i8 = tx + i * 256;
            cp16(kd + i8 * 16, ksrc + i8 * 8);
            cp16(vd + i8 * 16, vsrc + i8 * 8);
        }
    };
    cpKV(0, 0); CP_COMMIT(); CP_WAIT0();
    __syncthreads();

    float oacc[16][4];
    #pragma unroll
    for (int i = 0; i < 16; i++)
        #pragma unroll
        for (int r = 0; r < 4; r++) oacc[i][r] = 0.f;
    float m0 = -1e30f, m1 = -1e30f, l0 = 0.f, l1 = 0.f;

    for (int j = 0; j < jEnd; j++) {
        const int st = j & 1;
        const bool more = (j + 1 < jEnd);
        if (more) { cpKV(j + 1, st ^ 1); CP_COMMIT(); }

        float sacc[8][4];
        #pragma unroll
        for (int nt = 0; nt < 8; nt++)
            #pragma unroll
            for (int r = 0; r < 4; r++) sacc[nt][r] = 0.f;

        const __half* kb = smh + st * 8192;
        #pragma unroll
        for (int ks = 0; ks < 8; ks++) {
            #pragma unroll
            for (int np = 0; np < 4; np++) {
                uint4 t = *(const uint4*)(kb + ks * 1024 + np * 256 + lane * 8);
                uint32_t b0[2] = { t.x, t.y };
                uint32_t b1[2] = { t.z, t.w };
                mma_f16(sacc[2 * np],     qfr[ks], b0);
                mma_f16(sacc[2 * np + 1], qfr[ks], b1);
            }
        }

        const int keyBase = j * 64;
        float mt0 = -1e30f, mt1 = -1e30f;
        #pragma unroll
        for (int nt = 0; nt < 8; nt++) {
            const int kcol = keyBase + nt * 8 + 2 * lc;
            float2 mk = *(const float2*)&mrow[kcol];
            float s0 = sacc[nt][0] * scale + mk.x;
            float s1 = sacc[nt][1] * scale + mk.y;
            float s2 = sacc[nt][2] * scale + mk.x;
            float s3 = sacc[nt][3] * scale + mk.y;
            if (kcol     > r0g) s0 = -10000.f;
            if (kcol + 1 > r0g) s1 = -10000.f;
            if (kcol     > r1g) s2 = -10000.f;
            if (kcol + 1 > r1g) s3 = -10000.f;
            sacc[nt][0] = s0; sacc[nt][1] = s1; sacc[nt][2] = s2; sacc[nt][3] = s3;
            mt0 = fmaxf(mt0, fmaxf(s0, s1));
            mt1 = fmaxf(mt1, fmaxf(s2, s3));
        }
        mt0 = fmaxf(mt0, __shfl_xor_sync(0xffffffffu, mt0, 1));
        mt0 = fmaxf(mt0, __shfl_xor_sync(0xffffffffu, mt0, 2));
        mt1 = fmaxf(mt1, __shfl_xor_sync(0xffffffffu, mt1, 1));
        mt1 = fmaxf(mt1, __shfl_xor_sync(0xffffffffu, mt1, 2));

        const float mn0 = fmaxf(m0, mt0), mn1 = fmaxf(m1, mt1);
        const float a0 = __expf(m0 - mn0), a1 = __expf(m1 - mn1);
        m0 = mn0; m1 = mn1;

        float ts0 = 0.f, ts1 = 0.f;
        #pragma unroll
        for (int nt = 0; nt < 8; nt++) {
            float p0 = __expf(sacc[nt][0] - mn0);
            float p1 = __expf(sacc[nt][1] - mn0);
            float p2 = __expf(sacc[nt][2] - mn1);
            float p3 = __expf(sacc[nt][3] - mn1);
            sacc[nt][0] = p0; sacc[nt][1] = p1; sacc[nt][2] = p2; sacc[nt][3] = p3;
            ts0 += p0 + p1;
            ts1 += p2 + p3;
        }
        ts0 += __shfl_xor_sync(0xffffffffu, ts0, 1);
        ts0 += __shfl_xor_sync(0xffffffffu, ts0, 2);
        ts1 += __shfl_xor_sync(0xffffffffu, ts1, 1);
        ts1 += __shfl_xor_sync(0xffffffffu, ts1, 2);
        l0 = l0 * a0 + ts0;
        l1 = l1 * a1 + ts1;

        #pragma unroll
        for (int nt = 0; nt < 16; nt++) {
            oacc[nt][0] *= a0; oacc[nt][1] *= a0;
            oacc[nt][2] *= a1; oacc[nt][3] *= a1;
        }

        const __half* vb = smh + 16384 + st * 8192;
        #pragma unroll
        for (int ks = 0; ks < 4; ks++) {
            uint32_t af[4];
            af[0] = h2u(__floats2half2_rn(sacc[2 * ks][0],     sacc[2 * ks][1]));
            af[1] = h2u(__floats2half2_rn(sacc[2 * ks][2],     sacc[2 * ks][3]));
            af[2] = h2u(__floats2half2_rn(sacc[2 * ks + 1][0], sacc[2 * ks + 1][1]));
            af[3] = h2u(__floats2half2_rn(sacc[2 * ks + 1][2], sacc[2 * ks + 1][3]));
            #pragma unroll
            for (int np = 0; np < 8; np++) {
                uint4 t = *(const uint4*)(vb + ks * 2048 + np * 256 + lane * 8);
                uint32_t b0[2] = { t.x, t.y };
                uint32_t b1[2] = { t.z, t.w };
                mma_f16(oacc[2 * np],     af, b0);
                mma_f16(oacc[2 * np + 1], af, b1);
            }
        }

        if (more) { CP_WAIT0(); __syncthreads(); }
    }

    const float inv0 = 1.0f / l0;
    const float inv1 = 1.0f / l1;
    const size_t o0 = ((size_t)b * S_ + r0g) * H_ + h * 128 + 2 * lc;
    const size_t o1 = ((size_t)b * S_ + r1g) * H_ + h * 128 + 2 * lc;
    const int mg = b * S_ + r0g;
    #pragma unroll
    for (int nt = 0; nt < 16; nt++) {
        float v0 = oacc[nt][0] * inv0, v1 = oacc[nt][1] * inv0;
        float v2 = oacc[nt][2] * inv1, v3 = oacc[nt][3] * inv1;
        *(float2*)(ctx + o0 + nt * 8) = make_float2(v0, v1);
        *(float2*)(ctx + o1 + nt * 8) = make_float2(v2, v3);
        const int k0 = h * 128 + nt * 8 + 2 * lc;
        __half2 h01 = __floats2half2_rn(v0, v1);
        __half2 h23 = __floats2half2_rn(v2, v3);
        uint2 u = make_uint2(h2u(h01), h2u(h23));
        *(uint2*)&ctxp[afragH(mg, k0)] = u;
    }
}

// ---------------------------------------------------------------------------
extern "C" void kernel_launch(void* const* d_in, const int* in_sizes, int n_in,
                              void* d_out, int out_size)
{
    const float* x    = (const float*)d_in[0];
    const float* mask = (const float*)d_in[1];
    const float* qkvw = (const float*)d_in[2];
    const float* qkvb = (const float*)d_in[3];
    const float* ow   = (const float*)d_in[4];
    const float* nw   = (const float*)d_in[5];
    const float* nb   = (const float*)d_in[6];

    float* out     = (float*)d_out;
    float* out_o   = out;
    float* out_k   = out + 1 * BSH;
    float* out_v   = out + 2 * BSH;
    float* out_ctx = out + 3 * BSH;
    float* out_ln  = out + 4 * BSH;

    __half *qfr, *kfr, *vfr, *lnp, *ctxp, *qkvwP, *owP;
    cudaGetSymbolAddress((void**)&qfr,   g_qfr);
    cudaGetSymbolAddress((void**)&kfr,   g_kfr);
    cudaGetSymbolAddress((void**)&vfr,   g_vfr);
    cudaGetSymbolAddress((void**)&lnp,   g_lnp);
    cudaGetSymbolAddress((void**)&ctxp,  g_ctxp);
    cudaGetSymbolAddress((void**)&qkvwP, g_qkvwP);
    cudaGetSymbolAddress((void**)&owP,   g_owP);

    cudaFuncSetAttribute(mma_gemm2<3>, cudaFuncAttributeMaxDynamicSharedMemorySize, GEMM_SMEM);
    cudaFuncSetAttribute(mma_gemm2<0>, cudaFuncAttributeMaxDynamicSharedMemorySize, GEMM_SMEM);
    cudaFuncSetAttribute(flash_kernel, cudaFuncAttributeMaxDynamicSharedMemorySize, FLASH_SMEM);

    const float scale = 1.0f / sqrtf((float)DH);

    prep_b<<<dim3(KT_A, 3 * H_ / 32), 256>>>(qkvw, qkvwP, 3 * H_);
    prep_b<<<dim3(KT_A, H_ / 32), 256>>>(ow, owP, H_);

    ln_kernel<<<B_ * S_, 256>>>(x, nw, nb, out_ln, lnp);

    mma_gemm2<3><<<dim3(24, 32), 256, GEMM_SMEM>>>(
        lnp, qkvwP, nullptr, qfr, out_k, out_v, kfr, vfr, qkvb, 3 * H_);

    flash_kernel<<<dim3(16, BH), 256, FLASH_SMEM>>>(
        qfr, kfr, vfr, mask, out_ctx, ctxp, scale);

    mma_gemm2<0><<<dim3(8, 32), 256, GEMM_SMEM>>>(
        ctxp, owP, out_o, nullptr, nullptr, nullptr, nullptr, nullptr, nullptr, H_);
}

// round 13
// speedup vs baseline: 1.1040x; 1.1040x over previous
#include <cuda_runtime.h>
#include <cuda_fp16.h>
#include <cstdint>
#include <math.h>

#define B_    2
#define S_    2048
#define H_    2048
#define HEADS 16
#define DH    128
#define BH    (B_*HEADS)
#define BSH   ((size_t)B_*S_*H_)
#define KT_A  64

// ---------------------------------------------------------------------------
__device__ __half g_qfr[BSH];                    // Q flash-A-frags fp16
__device__ __half g_kfr[BSH];                    // K flash-B-frags fp16
__device__ __half g_vfr[BSH];                    // V flash-B-frags fp16
__device__ __half g_lnp[BSH];                    // LN out, GEMM-A-frag fp16
__device__ __half g_ctxp[BSH];                   // ctx,    GEMM-A-frag fp16
__device__ __half g_qkvwP[(size_t)3*H_*H_];      // qkvw, B-frag fp16
__device__ __half g_owP[(size_t)H_*H_];          // ow,   B-frag fp16

// ---------------------------------------------------------------------------
__device__ __forceinline__ uint32_t h2u(__half2 h) { return *(uint32_t*)&h; }
__device__ __forceinline__ void mma_f16(float* c, const uint32_t* a, const uint32_t* b) {
    asm volatile(
        "mma.sync.aligned.m16n8k16.row.col.f32.f16.f16.f32 "
        "{%0,%1,%2,%3},{%4,%5,%6,%7},{%8,%9},{%0,%1,%2,%3};\n"
        : "+f"(c[0]), "+f"(c[1]), "+f"(c[2]), "+f"(c[3])
        : "r"(a[0]), "r"(a[1]), "r"(a[2]), "r"(a[3]), "r"(b[0]), "r"(b[1]));
}
__device__ __forceinline__ void cp16(uint32_t dst, const void* src) {
    asm volatile("cp.async.cg.shared.global [%0], [%1], 16;\n" :: "r"(dst), "l"(src));
}
#define CP_COMMIT() asm volatile("cp.async.commit_group;\n")
#define CP_WAIT0()  asm volatile("cp.async.wait_group 0;\n")
#define CP_WAIT1()  asm volatile("cp.async.wait_group 1;\n")

// fp16 GEMM A-fragment index (m16n8k16), K=2048
__device__ __forceinline__ size_t afragH(int m, int k) {
    return ((size_t)((m >> 4) * KT_A + (k >> 5))) * 512
         + (((k >> 4) & 1) * 256)
         + (((m & 7) * 4 + ((k >> 1) & 3)) * 8)
         + ((((k >> 3) & 1) * 2 + ((m >> 3) & 1)) * 2)
         + (k & 1);
}

// ---------------------------------------------------------------------------
// Weight prep: w[K][N] -> fp16 B-frag chunks [n32][kt]: 1024 halfs
// ---------------------------------------------------------------------------
__global__ void __launch_bounds__(256) prep_b(
    const float* __restrict__ w, __half* __restrict__ out, int N)
{
    const int kt = blockIdx.x, n32 = blockIdx.y;
    __shared__ float sm[32][33];
    const int tx = threadIdx.x;
    const int kl = tx >> 5, nl = tx & 31;
    #pragma unroll
    for (int i = 0; i < 32; i += 8)
        sm[kl + i][nl] = w[(size_t)(kt * 32 + kl + i) * N + n32 * 32 + nl];
    __syncthreads();
    const size_t base = ((size_t)n32 * KT_A + kt) * 1024;
    #pragma unroll
    for (int e = tx; e < 1024; e += 256) {
        const int k = e >> 5, n = e & 31;
        const int off = ((k >> 4) * 512) + (((k >> 3) & 1) * 256)
                      + (((n & 7) * 4 + ((k >> 1) & 3)) * 8)
                      + ((n >> 3) * 2) + (k & 1);
        out[base + off] = __float2half_rn(sm[k][n]);
    }
}

// ---------------------------------------------------------------------------
// LayerNorm: exact y + fp16 GEMM-A-frag copy
// ---------------------------------------------------------------------------
__global__ void __launch_bounds__(256) ln_kernel(
    const float* __restrict__ x, const float* __restrict__ g,
    const float* __restrict__ b, float* __restrict__ y, __half* __restrict__ yp)
{
    const int row = blockIdx.x;
    const float* xr = x + (size_t)row * H_;
    float s = 0.f, ss = 0.f;
    for (int i = threadIdx.x; i < H_; i += 256) {
        float t = xr[i];
        s += t; ss += t * t;
    }
    #pragma unroll
    for (int o = 16; o; o >>= 1) {
        s  += __shfl_xor_sync(0xffffffffu, s,  o);
        ss += __shfl_xor_sync(0xffffffffu, ss, o);
    }
    __shared__ float red[2][8];
    const int w = threadIdx.x >> 5, l = threadIdx.x & 31;
    if (l == 0) { red[0][w] = s; red[1][w] = ss; }
    __syncthreads();
    __shared__ float stats[2];
    if (threadIdx.x == 0) {
        float S = 0.f, SS = 0.f;
        #pragma unroll
        for (int i = 0; i < 8; i++) { S += red[0][i]; SS += red[1][i]; }
        float mu  = S / (float)H_;
        float var = SS / (float)H_ - mu * mu;
        stats[0] = mu;
        stats[1] = rsqrtf(var + 1e-12f);
    }
    __syncthreads();
    const float mu = stats[0], rstd = stats[1];
    float* yr = y + (size_t)row * H_;
    for (int i = threadIdx.x; i < H_; i += 256) {
        float v = (xr[i] - mu) * rstd * g[i] + b[i];
        yr[i] = v;
        yp[afragH(row, i)] = __float2half_rn(v);
    }
}

// ---------------------------------------------------------------------------
// FP16 mma.sync GEMM: CTA 128x128, 8 warps (2Mx4N, warp tile 64x32),
// pipeline stage = K-slab of 64 (two 32-K fragment chunks), 3 stages,
// 2 CTAs/SM. EPI: 0 plain C; 3 QKV scatter (flash frags + exact k/v + bias).
// ---------------------------------------------------------------------------
#define STG_HALFS 16384                   // A 8192 + B 8192 halfs = 32 KB
#define GEMM_SMEM (3 * STG_HALFS * 2)     // 98304 B

template<int EPI>
__global__ void __launch_bounds__(256, 2) mma_gemm2(
    const __half* __restrict__ Ap, const __half* __restrict__ Bp,
    float* __restrict__ C,
    __half* __restrict__ Qf, float* __restrict__ Ck, float* __restrict__ Cv,
    __half* __restrict__ Kf, __half* __restrict__ Vf,
    const float* __restrict__ bias, int Ntot)
{
    const int m16g0 = blockIdx.y * 8;
    const int n32g0 = blockIdx.x * 4;
    const int rowBase = blockIdx.y * 128;
    const int colBase = blockIdx.x * 128;

    extern __shared__ __half smh[];
    const uint32_t smemU = (uint32_t)__cvta_generic_to_shared(smh);

    const int tx = threadIdx.x;
    const int lane = tx & 31, warp = tx >> 5;
    const int wm = (warp >> 2) * 64;
    const int wn = (warp & 3) * 32;
    const int lr = lane >> 2;
    const int lc = lane & 3;

    // One stage = K-slab of 64: A 8 chunks x 1024 halfs, B 4 chunks x 2048 halfs
    auto loadStage = [&](int t, int st) {
        const uint32_t sbase = smemU + st * STG_HALFS * 2;
        #pragma unroll
        for (int i = 0; i < 8; i++) {
            const int idx = tx + i * 256;          // uint4 index 0..2047
            if (idx < 1024) {                       // A: chunk g, 128 uint4 each
                const int g = idx >> 7, rem = idx & 127;
                cp16(sbase + idx * 16,
                     Ap + ((size_t)(m16g0 + g) * KT_A + 2 * t) * 512 + rem * 8);
            } else {                                // B: chunk nb, 256 uint4 each
                const int j = idx - 1024;
                const int nb = j >> 8, rem = j & 255;
                cp16(sbase + idx * 16,
                     Bp + ((size_t)(n32g0 + nb) * KT_A + 2 * t) * 1024 + rem * 8);
            }
        }
    };

    float acc[4][4][4];
    #pragma unroll
    for (int i = 0; i < 4; i++)
        #pragma unroll
        for (int j = 0; j < 4; j++)
            #pragma unroll
            for (int r = 0; r < 4; r++) acc[i][j][r] = 0.f;

    loadStage(0, 0); CP_COMMIT();
    loadStage(1, 1); CP_COMMIT();

    const int T = KT_A / 2;   // 32 stages
    for (int t = 0; t < T; t++) {
        const int st = t % 3;
        CP_WAIT1();
        __syncthreads();
        if (t + 2 < T) { loadStage(t + 2, (t + 2) % 3); CP_COMMIT(); }

        const __half* sf = smh + st * STG_HALFS;
        const __half* aB = sf + (warp >> 2) * 4096;          // 4 m16-chunks (x1024)
        const __half* bB = sf + 8192 + (warp & 3) * 2048;    // 1 n32-chunk (x2048)

        #pragma unroll
        for (int sub = 0; sub < 2; sub++) {       // two 32-K chunks, in kt order
            #pragma unroll
            for (int ks = 0; ks < 2; ks++) {
                uint32_t af[4][4];
                #pragma unroll
                for (int mt = 0; mt < 4; mt++) {
                    uint4 v = *(const uint4*)(aB + mt * 1024 + sub * 512
                                              + ks * 256 + lane * 8);
                    af[mt][0] = v.x; af[mt][1] = v.y; af[mt][2] = v.z; af[mt][3] = v.w;
                }
                uint4 tb0 = *(const uint4*)(bB + sub * 1024 + ks * 512 + lane * 8);
                uint4 tb1 = *(const uint4*)(bB + sub * 1024 + ks * 512 + 256 + lane * 8);
                uint32_t bf[4][2];
                bf[0][0] = tb0.x; bf[0][1] = tb1.x;
                bf[1][0] = tb0.y; bf[1][1] = tb1.y;
                bf[2][0] = tb0.z; bf[2][1] = tb1.z;
                bf[3][0] = tb0.w; bf[3][1] = tb1.w;
                #pragma unroll
                for (int mt = 0; mt < 4; mt++)
                    #pragma unroll
                    for (int nt = 0; nt < 4; nt++)
                        mma_f16(acc[mt][nt], af[mt], bf[nt]);
            }
        }
    }

    if (EPI == 3) {
        const int whichBlk = colBase >> 11;
        const int h = (colBase & 2047) >> 7;
        #pragma unroll
        for (int mt = 0; mt < 4; mt++) {
            #pragma unroll
            for (int nt = 0; nt < 4; nt++) {
                const int gn = colBase + wn + nt * 8 + 2 * lc;
                const int d  = gn & 127;
                const int m0 = rowBase + wm + mt * 16 + lr;
                const int b  = m0 >> 11, s = m0 & 2047;
                float* a = acc[mt][nt];
                const float v00 = a[0] + bias[gn], v01 = a[1] + bias[gn + 1];
                const float v10 = a[2] + bias[gn], v11 = a[3] + bias[gn + 1];
                if (whichBlk == 0) {
                    __half* qp = Qf
                        + (((((size_t)(b * 16 + h) * 16 + (s >> 7)) * 8 + ((s >> 4) & 7)) * 8
                            + (d >> 4)) * 256) + lane * 8 + ((d >> 3) & 1) * 4;
                    *(__half2*)(qp)     = __floats2half2_rn(v00, v01);
                    *(__half2*)(qp + 2) = __floats2half2_rn(v10, v11);
                } else {
                    float* base = (whichBlk == 1) ? Ck : Cv;
                    *(float2*)&base[((((size_t)b * 16 + h) << 11) + s) * 128 + d] =
                        make_float2(v00, v01);
                    *(float2*)&base[((((size_t)b * 16 + h) << 11) + s + 8) * 128 + d] =
                        make_float2(v10, v11);
                    if (whichBlk == 1) {
                        __half* kb = Kf + (((size_t)(b * 16 + h) * 32) + (s >> 6)) * 8192
                                   + (d >> 4) * 1024 + lane * 8 + ((d >> 3) & 1) * 2;
                        const int nt0 = (s & 63) >> 3;
                        *(__half2*)(kb + (nt0 >> 1) * 256 + (nt0 & 1) * 4) =
                            __floats2half2_rn(v00, v01);
                        const int nt1 = nt0 + 1;
                        *(__half2*)(kb + (nt1 >> 1) * 256 + (nt1 & 1) * 4) =
                            __floats2half2_rn(v10, v11);
                    } else {
                        const size_t vblk =
                            (((size_t)(b * 16 + h) * 32) + (s >> 6)) * 8192
                            + ((s & 63) >> 4) * 2048 + (d >> 4) * 256;
                        auto vst = [&](int ss, int dd, float val) {
                            const int la = (dd & 7) * 4 + ((ss >> 1) & 3);
                            Vf[vblk + la * 8 + ((dd >> 3) & 1) * 4
                               + ((ss & 15) >> 3) * 2 + (ss & 1)] = __float2half_rn(val);
                        };
                        vst(s, d, v00);     vst(s, d + 1, v01);
                        vst(s + 8, d, v10); vst(s + 8, d + 1, v11);
                    }
                }
            }
        }
        return;
    }

    #pragma unroll
    for (int mt = 0; mt < 4; mt++) {
        #pragma unroll
        for (int nt = 0; nt < 4; nt++) {
            const int gm = rowBase + wm + mt * 16 + lr;
            const int gn = colBase + wn + nt * 8 + 2 * lc;
            float* a = acc[mt][nt];
            #pragma unroll
            for (int r = 0; r < 2; r++)
                *(float2*)&C[(size_t)(gm + r * 8) * Ntot + gn] =
                    make_float2(a[r * 2 + 0], a[r * 2 + 1]);
        }
    }
}

// ---------------------------------------------------------------------------
// FP16 flash attention (unchanged from R10)
// ---------------------------------------------------------------------------
#define FLASH_SMEM (4 * 8192 * 2)

__global__ void __launch_bounds__(256, 1) flash_kernel(
    const __half* __restrict__ qf, const __half* __restrict__ kf,
    const __half* __restrict__ vf, const float* __restrict__ mask,
    float* __restrict__ ctx, __half* __restrict__ ctxp, float scale)
{
    const int qi = gridDim.x - 1 - blockIdx.x;
    const int rowBase = qi * 128;
    const int bh = blockIdx.y;
    const int b = bh >> 4, h = bh & 15;

    const __half* Kg = kf + (size_t)bh * 32 * 8192;
    const __half* Vg = vf + (size_t)bh * 32 * 8192;
    const float* mrow = mask + (size_t)b * S_;

    extern __shared__ __half smh[];
    const uint32_t smemU = (uint32_t)__cvta_generic_to_shared(smh);

    const int tx = threadIdx.x;
    const int lane = tx & 31, wid = tx >> 5;
    const int lr = lane >> 2, lc = lane & 3;
    const int r0g = rowBase + wid * 16 + lr;
    const int r1g = r0g + 8;

    uint32_t qfr[8][4];
    {
        const __half* Qg = qf + (((size_t)bh * 16 + qi) * 8 + wid) * 2048 + lane * 8;
        #pragma unroll
        for (int ks = 0; ks < 8; ks++) {
            uint4 t = *(const uint4*)(Qg + ks * 256);
            qfr[ks][0] = t.x; qfr[ks][1] = t.y; qfr[ks][2] = t.z; qfr[ks][3] = t.w;
        }
    }

    const int jEnd = 2 * qi + 2;
    auto cpKV = [&](int j, int st) {
        const __half* ksrc = Kg + (size_t)j * 8192;
        const __half* vsrc = Vg + (size_t)j * 8192;
        const uint32_t kd = smemU + st * 16384;
        const uint32_t vd = smemU + 32768 + st * 16384;
        #pragma unroll
        for (int i = 0; i < 4; i++) {
            const int i8 = tx + i * 256;
            cp16(kd + i8 * 16, ksrc + i8 * 8);
            cp16(vd + i8 * 16, vsrc + i8 * 8);
        }
    };
    cpKV(0, 0); CP_COMMIT(); CP_WAIT0();
    __syncthreads();

    float oacc[16][4];
    #pragma unroll
    for (int i = 0; i < 16; i++)
        #pragma unroll
        for (int r = 0; r < 4; r++) oacc[i][r] = 0.f;
    float m0 = -1e30f, m1 = -1e30f, l0 = 0.f, l1 = 0.f;

    for (int j = 0; j < jEnd; j++) {
        const int st = j & 1;
        const bool more = (j + 1 < jEnd);
        if (more) { cpKV(j + 1, st ^ 1); CP_COMMIT(); }

        float sacc[8][4];
        #pragma unroll
        for (int nt = 0; nt < 8; nt++)
            #pragma unroll
            for (int r = 0; r < 4; r++) sacc[nt][r] = 0.f;

        const __half* kb = smh + st * 8192;
        #pragma unroll
        for (int ks = 0; ks < 8; ks++) {
            #pragma unroll
            for (int np = 0; np < 4; np++) {
                uint4 t = *(const uint4*)(kb + ks * 1024 + np * 256 + lane * 8);
                uint32_t b0[2] = { t.x, t.y };
                uint32_t b1[2] = { t.z, t.w };
                mma_f16(sacc[2 * np],     qfr[ks], b0);
                mma_f16(sacc[2 * np + 1], qfr[ks], b1);
            }
        }

        const int keyBase = j * 64;
        float mt0 = -1e30f, mt1 = -1e30f;
        #pragma unroll
        for (int nt = 0; nt < 8; nt++) {
            const int kcol = keyBase + nt * 8 + 2 * lc;
            float2 mk = *(const float2*)&mrow[kcol];
            float s0 = sacc[nt][0] * scale + mk.x;
            float s1 = sacc[nt][1] * scale + mk.y;
            float s2 = sacc[nt][2] * scale + mk.x;
            float s3 = sacc[nt][3] * scale + mk.y;
            if (kcol     > r0g) s0 = -10000.f;
            if (kcol + 1 > r0g) s1 = -10000.f;
            if (kcol     > r1g) s2 = -10000.f;
            if (kcol + 1 > r1g) s3 = -10000.f;
            sacc[nt][0] = s0; sacc[nt][1] = s1; sacc[nt][2] = s2; sacc[nt][3] = s3;
            mt0 = fmaxf(mt0, fmaxf(s0, s1));
            mt1 = fmaxf(mt1, fmaxf(s2, s3));
        }
        mt0 = fmaxf(mt0, __shfl_xor_sync(0xffffffffu, mt0, 1));
        mt0 = fmaxf(mt0, __shfl_xor_sync(0xffffffffu, mt0, 2));
        mt1 = fmaxf(mt1, __shfl_xor_sync(0xffffffffu, mt1, 1));
        mt1 = fmaxf(mt1, __shfl_xor_sync(0xffffffffu, mt1, 2));

        const float mn0 = fmaxf(m0, mt0), mn1 = fmaxf(m1, mt1);
        const float a0 = __expf(m0 - mn0), a1 = __expf(m1 - mn1);
        m0 = mn0; m1 = mn1;

        float ts0 = 0.f, ts1 = 0.f;
        #pragma unroll
        for (int nt = 0; nt < 8; nt++) {
            float p0 = __expf(sacc[nt][0] - mn0);
            float p1 = __expf(sacc[nt][1] - mn0);
            float p2 = __expf(sacc[nt][2] - mn1);
            float p3 = __expf(sacc[nt][3] - mn1);
            sacc[nt][0] = p0; sacc[nt][1] = p1; sacc[nt][2] = p2; sacc[nt][3] = p3;
            ts0 += p0 + p1;
            ts1 += p2 + p3;
        }
        ts0 += __shfl_xor_sync(0xffffffffu, ts0, 1);
        ts0 += __shfl_xor_sync(0xffffffffu, ts0, 2);
        ts1 += __shfl_xor_sync(0xffffffffu, ts1, 1);
        ts1 += __shfl_xor_sync(0xffffffffu, ts1, 2);
        l0 = l0 * a0 + ts0;
        l1 = l1 * a1 + ts1;

        #pragma unroll
        for (int nt = 0; nt < 16; nt++) {
            oacc[nt][0] *= a0; oacc[nt][1] *= a0;
            oacc[nt][2] *= a1; oacc[nt][3] *= a1;
        }

        const __half* vb = smh + 16384 + st * 8192;
        #pragma unroll
        for (int ks = 0; ks < 4; ks++) {
            uint32_t af[4];
            af[0] = h2u(__floats2half2_rn(sacc[2 * ks][0],     sacc[2 * ks][1]));
            af[1] = h2u(__floats2half2_rn(sacc[2 * ks][2],     sacc[2 * ks][3]));
            af[2] = h2u(__floats2half2_rn(sacc[2 * ks + 1][0], sacc[2 * ks + 1][1]));
            af[3] = h2u(__floats2half2_rn(sacc[2 * ks + 1][2], sacc[2 * ks + 1][3]));
            #pragma unroll
            for (int np = 0; np < 8; np++) {
                uint4 t = *(const uint4*)(vb + ks * 2048 + np * 256 + lane * 8);
                uint32_t b0[2] = { t.x, t.y };
                uint32_t b1[2] = { t.z, t.w };
                mma_f16(oacc[2 * np],     af, b0);
                mma_f16(oacc[2 * np + 1], af, b1);
            }
        }

        if (more) { CP_WAIT0(); __syncthreads(); }
    }

    const float inv0 = 1.0f / l0;
    const float inv1 = 1.0f / l1;
    const size_t o0 = ((size_t)b * S_ + r0g) * H_ + h * 128 + 2 * lc;
    const size_t o1 = ((size_t)b * S_ + r1g) * H_ + h * 128 + 2 * lc;
    const int mg = b * S_ + r0g;
    #pragma unroll
    for (int nt = 0; nt < 16; nt++) {
        float v0 = oacc[nt][0] * inv0, v1 = oacc[nt][1] * inv0;
        float v2 = oacc[nt][2] * inv1, v3 = oacc[nt][3] * inv1;
        *(float2*)(ctx + o0 + nt * 8) = make_float2(v0, v1);
        *(float2*)(ctx + o1 + nt * 8) = make_float2(v2, v3);
        const int k0 = h * 128 + nt * 8 + 2 * lc;
        __half2 h01 = __floats2half2_rn(v0, v1);
        __half2 h23 = __floats2half2_rn(v2, v3);
        uint2 u = make_uint2(h2u(h01), h2u(h23));
        *(uint2*)&ctxp[afragH(mg, k0)] = u;
    }
}

// ---------------------------------------------------------------------------
extern "C" void kernel_launch(void* const* d_in, const int* in_sizes, int n_in,
                              void* d_out, int out_size)
{
    const float* x    = (const float*)d_in[0];
    const float* mask = (const float*)d_in[1];
    const float* qkvw = (const float*)d_in[2];
    const float* qkvb = (const float*)d_in[3];
    const float* ow   = (const float*)d_in[4];
    const float* nw   = (const float*)d_in[5];
    const float* nb   = (const float*)d_in[6];

    float* out     = (float*)d_out;
    float* out_o   = out;
    float* out_k   = out + 1 * BSH;
    float* out_v   = out + 2 * BSH;
    float* out_ctx = out + 3 * BSH;
    float* out_ln  = out + 4 * BSH;

    __half *qfr, *kfr, *vfr, *lnp, *ctxp, *qkvwP, *owP;
    cudaGetSymbolAddress((void**)&qfr,   g_qfr);
    cudaGetSymbolAddress((void**)&kfr,   g_kfr);
    cudaGetSymbolAddress((void**)&vfr,   g_vfr);
    cudaGetSymbolAddress((void**)&lnp,   g_lnp);
    cudaGetSymbolAddress((void**)&ctxp,  g_ctxp);
    cudaGetSymbolAddress((void**)&qkvwP, g_qkvwP);
    cudaGetSymbolAddress((void**)&owP,   g_owP);

    cudaFuncSetAttribute(mma_gemm2<3>, cudaFuncAttributeMaxDynamicSharedMemorySize, GEMM_SMEM);
    cudaFuncSetAttribute(mma_gemm2<0>, cudaFuncAttributeMaxDynamicSharedMemorySize, GEMM_SMEM);
    cudaFuncSetAttribute(flash_kernel, cudaFuncAttributeMaxDynamicSharedMemorySize, FLASH_SMEM);

    const float scale = 1.0f / sqrtf((float)DH);

    prep_b<<<dim3(KT_A, 3 * H_ / 32), 256>>>(qkvw, qkvwP, 3 * H_);
    prep_b<<<dim3(KT_A, H_ / 32), 256>>>(ow, owP, H_);

    ln_kernel<<<B_ * S_, 256>>>(x, nw, nb, out_ln, lnp);

    mma_gemm2<3><<<dim3(48, 32), 256, GEMM_SMEM>>>(
        lnp, qkvwP, nullptr, qfr, out_k, out_v, kfr, vfr, qkvb, 3 * H_);

    flash_kernel<<<dim3(16, BH), 256, FLASH_SMEM>>>(
        qfr, kfr, vfr, mask, out_ctx, ctxp, scale);

    mma_gemm2<0><<<dim3(16, 32), 256, GEMM_SMEM>>>(
        ctxp, owP, out_o, nullptr, nullptr, nullptr, nullptr, nullptr, nullptr, H_);
}

// round 14
// speedup vs baseline: 1.1418x; 1.0342x over previous
#include <cuda_runtime.h>
#include <cuda_fp16.h>
#include <cstdint>
#include <math.h>

#define B_    2
#define S_    2048
#define H_    2048
#define HEADS 16
#define DH    128
#define BH    (B_*HEADS)
#define BSH   ((size_t)B_*S_*H_)
#define KT_A  64

// ---------------------------------------------------------------------------
__device__ __half g_qfr[BSH];                    // Q flash-A-frags fp16
__device__ __half g_kfr[BSH];                    // K flash-B-frags fp16
__device__ __half g_vfr[BSH];                    // V flash-B-frags fp16
__device__ __half g_lnp[BSH];                    // LN out, GEMM-A-frag fp16
__device__ __half g_ctxp[BSH];                   // ctx,    GEMM-A-frag fp16
__device__ __half g_qkvwP[(size_t)3*H_*H_];      // qkvw, B-frag fp16
__device__ __half g_owP[(size_t)H_*H_];          // ow,   B-frag fp16

// ---------------------------------------------------------------------------
__device__ __forceinline__ uint32_t h2u(__half2 h) { return *(uint32_t*)&h; }
__device__ __forceinline__ void mma_f16(float* c, const uint32_t* a, const uint32_t* b) {
    asm volatile(
        "mma.sync.aligned.m16n8k16.row.col.f32.f16.f16.f32 "
        "{%0,%1,%2,%3},{%4,%5,%6,%7},{%8,%9},{%0,%1,%2,%3};\n"
        : "+f"(c[0]), "+f"(c[1]), "+f"(c[2]), "+f"(c[3])
        : "r"(a[0]), "r"(a[1]), "r"(a[2]), "r"(a[3]), "r"(b[0]), "r"(b[1]));
}
__device__ __forceinline__ void cp16(uint32_t dst, const void* src) {
    asm volatile("cp.async.cg.shared.global [%0], [%1], 16;\n" :: "r"(dst), "l"(src));
}
#define CP_COMMIT() asm volatile("cp.async.commit_group;\n")
#define CP_WAIT0()  asm volatile("cp.async.wait_group 0;\n")
#define CP_WAIT1()  asm volatile("cp.async.wait_group 1;\n")

// fp16 GEMM A-fragment index (m16n8k16), K=2048
__device__ __forceinline__ size_t afragH(int m, int k) {
    return ((size_t)((m >> 4) * KT_A + (k >> 5))) * 512
         + (((k >> 4) & 1) * 256)
         + (((m & 7) * 4 + ((k >> 1) & 3)) * 8)
         + ((((k >> 3) & 1) * 2 + ((m >> 3) & 1)) * 2)
         + (k & 1);
}

// ---------------------------------------------------------------------------
// Weight prep: w[K][N] -> fp16 B-frag chunks [n32][kt]: 1024 halfs
// ---------------------------------------------------------------------------
__global__ void __launch_bounds__(256) prep_b(
    const float* __restrict__ w, __half* __restrict__ out, int N)
{
    const int kt = blockIdx.x, n32 = blockIdx.y;
    __shared__ float sm[32][33];
    const int tx = threadIdx.x;
    const int kl = tx >> 5, nl = tx & 31;
    #pragma unroll
    for (int i = 0; i < 32; i += 8)
        sm[kl + i][nl] = w[(size_t)(kt * 32 + kl + i) * N + n32 * 32 + nl];
    __syncthreads();
    const size_t base = ((size_t)n32 * KT_A + kt) * 1024;
    #pragma unroll
    for (int e = tx; e < 1024; e += 256) {
        const int k = e >> 5, n = e & 31;
        const int off = ((k >> 4) * 512) + (((k >> 3) & 1) * 256)
                      + (((n & 7) * 4 + ((k >> 1) & 3)) * 8)
                      + ((n >> 3) * 2) + (k & 1);
        out[base + off] = __float2half_rn(sm[k][n]);
    }
}

// ---------------------------------------------------------------------------
// LayerNorm: exact y + fp16 GEMM-A-frag copy
// ---------------------------------------------------------------------------
__global__ void __launch_bounds__(256) ln_kernel(
    const float* __restrict__ x, const float* __restrict__ g,
    const float* __restrict__ b, float* __restrict__ y, __half* __restrict__ yp)
{
    const int row = blockIdx.x;
    const float* xr = x + (size_t)row * H_;
    float s = 0.f, ss = 0.f;
    for (int i = threadIdx.x; i < H_; i += 256) {
        float t = xr[i];
        s += t; ss += t * t;
    }
    #pragma unroll
    for (int o = 16; o; o >>= 1) {
        s  += __shfl_xor_sync(0xffffffffu, s,  o);
        ss += __shfl_xor_sync(0xffffffffu, ss, o);
    }
    __shared__ float red[2][8];
    const int w = threadIdx.x >> 5, l = threadIdx.x & 31;
    if (l == 0) { red[0][w] = s; red[1][w] = ss; }
    __syncthreads();
    __shared__ float stats[2];
    if (threadIdx.x == 0) {
        float S = 0.f, SS = 0.f;
        #pragma unroll
        for (int i = 0; i < 8; i++) { S += red[0][i]; SS += red[1][i]; }
        float mu  = S / (float)H_;
        float var = SS / (float)H_ - mu * mu;
        stats[0] = mu;
        stats[1] = rsqrtf(var + 1e-12f);
    }
    __syncthreads();
    const float mu = stats[0], rstd = stats[1];
    float* yr = y + (size_t)row * H_;
    for (int i = threadIdx.x; i < H_; i += 256) {
        float v = (xr[i] - mu) * rstd * g[i] + b[i];
        yr[i] = v;
        yp[afragH(row, i)] = __float2half_rn(v);
    }
}

// ---------------------------------------------------------------------------
// FP16 mma.sync GEMM (identical to R13): CTA 128x128, K-slab 64, 3 stages,
// 2 CTAs/SM. EPI: 0 plain C; 3 QKV scatter (flash frags + exact k/v + bias).
// ---------------------------------------------------------------------------
#define STG_HALFS 16384
#define GEMM_SMEM (3 * STG_HALFS * 2)

template<int EPI>
__global__ void __launch_bounds__(256, 2) mma_gemm2(
    const __half* __restrict__ Ap, const __half* __restrict__ Bp,
    float* __restrict__ C,
    __half* __restrict__ Qf, float* __restrict__ Ck, float* __restrict__ Cv,
    __half* __restrict__ Kf, __half* __restrict__ Vf,
    const float* __restrict__ bias, int Ntot)
{
    const int m16g0 = blockIdx.y * 8;
    const int n32g0 = blockIdx.x * 4;
    const int rowBase = blockIdx.y * 128;
    const int colBase = blockIdx.x * 128;

    extern __shared__ __half smh[];
    const uint32_t smemU = (uint32_t)__cvta_generic_to_shared(smh);

    const int tx = threadIdx.x;
    const int lane = tx & 31, warp = tx >> 5;
    const int wm = (warp >> 2) * 64;
    const int wn = (warp & 3) * 32;
    const int lr = lane >> 2;
    const int lc = lane & 3;

    auto loadStage = [&](int t, int st) {
        const uint32_t sbase = smemU + st * STG_HALFS * 2;
        #pragma unroll
        for (int i = 0; i < 8; i++) {
            const int idx = tx + i * 256;
            if (idx < 1024) {
                const int g = idx >> 7, rem = idx & 127;
                cp16(sbase + idx * 16,
                     Ap + ((size_t)(m16g0 + g) * KT_A + 2 * t) * 512 + rem * 8);
            } else {
                const int j = idx - 1024;
                const int nb = j >> 8, rem = j & 255;
                cp16(sbase + idx * 16,
                     Bp + ((size_t)(n32g0 + nb) * KT_A + 2 * t) * 1024 + rem * 8);
            }
        }
    };

    float acc[4][4][4];
    #pragma unroll
    for (int i = 0; i < 4; i++)
        #pragma unroll
        for (int j = 0; j < 4; j++)
            #pragma unroll
            for (int r = 0; r < 4; r++) acc[i][j][r] = 0.f;

    loadStage(0, 0); CP_COMMIT();
    loadStage(1, 1); CP_COMMIT();

    const int T = KT_A / 2;
    for (int t = 0; t < T; t++) {
        const int st = t % 3;
        CP_WAIT1();
        __syncthreads();
        if (t + 2 < T) { loadStage(t + 2, (t + 2) % 3); CP_COMMIT(); }

        const __half* sf = smh + st * STG_HALFS;
        const __half* aB = sf + (warp >> 2) * 4096;
        const __half* bB = sf + 8192 + (warp & 3) * 2048;

        #pragma unroll
        for (int sub = 0; sub < 2; sub++) {
            #pragma unroll
            for (int ks = 0; ks < 2; ks++) {
                uint32_t af[4][4];
                #pragma unroll
                for (int mt = 0; mt < 4; mt++) {
                    uint4 v = *(const uint4*)(aB + mt * 1024 + sub * 512
                                              + ks * 256 + lane * 8);
                    af[mt][0] = v.x; af[mt][1] = v.y; af[mt][2] = v.z; af[mt][3] = v.w;
                }
                uint4 tb0 = *(const uint4*)(bB + sub * 1024 + ks * 512 + lane * 8);
                uint4 tb1 = *(const uint4*)(bB + sub * 1024 + ks * 512 + 256 + lane * 8);
                uint32_t bf[4][2];
                bf[0][0] = tb0.x; bf[0][1] = tb1.x;
                bf[1][0] = tb0.y; bf[1][1] = tb1.y;
                bf[2][0] = tb0.z; bf[2][1] = tb1.z;
                bf[3][0] = tb0.w; bf[3][1] = tb1.w;
                #pragma unroll
                for (int mt = 0; mt < 4; mt++)
                    #pragma unroll
                    for (int nt = 0; nt < 4; nt++)
                        mma_f16(acc[mt][nt], af[mt], bf[nt]);
            }
        }
    }

    if (EPI == 3) {
        const int whichBlk = colBase >> 11;
        const int h = (colBase & 2047) >> 7;
        #pragma unroll
        for (int mt = 0; mt < 4; mt++) {
            #pragma unroll
            for (int nt = 0; nt < 4; nt++) {
                const int gn = colBase + wn + nt * 8 + 2 * lc;
                const int d  = gn & 127;
                const int m0 = rowBase + wm + mt * 16 + lr;
                const int b  = m0 >> 11, s = m0 & 2047;
                float* a = acc[mt][nt];
                const float v00 = a[0] + bias[gn], v01 = a[1] + bias[gn + 1];
                const float v10 = a[2] + bias[gn], v11 = a[3] + bias[gn + 1];
                if (whichBlk == 0) {
                    __half* qp = Qf
                        + (((((size_t)(b * 16 + h) * 16 + (s >> 7)) * 8 + ((s >> 4) & 7)) * 8
                            + (d >> 4)) * 256) + lane * 8 + ((d >> 3) & 1) * 4;
                    *(__half2*)(qp)     = __floats2half2_rn(v00, v01);
                    *(__half2*)(qp + 2) = __floats2half2_rn(v10, v11);
                } else {
                    float* base = (whichBlk == 1) ? Ck : Cv;
                    *(float2*)&base[((((size_t)b * 16 + h) << 11) + s) * 128 + d] =
                        make_float2(v00, v01);
                    *(float2*)&base[((((size_t)b * 16 + h) << 11) + s + 8) * 128 + d] =
                        make_float2(v10, v11);
                    if (whichBlk == 1) {
                        __half* kb = Kf + (((size_t)(b * 16 + h) * 32) + (s >> 6)) * 8192
                                   + (d >> 4) * 1024 + lane * 8 + ((d >> 3) & 1) * 2;
                        const int nt0 = (s & 63) >> 3;
                        *(__half2*)(kb + (nt0 >> 1) * 256 + (nt0 & 1) * 4) =
                            __floats2half2_rn(v00, v01);
                        const int nt1 = nt0 + 1;
                        *(__half2*)(kb + (nt1 >> 1) * 256 + (nt1 & 1) * 4) =
                            __floats2half2_rn(v10, v11);
                    } else {
                        const size_t vblk =
                            (((size_t)(b * 16 + h) * 32) + (s >> 6)) * 8192
                            + ((s & 63) >> 4) * 2048 + (d >> 4) * 256;
                        auto vst = [&](int ss, int dd, float val) {
                            const int la = (dd & 7) * 4 + ((ss >> 1) & 3);
                            Vf[vblk + la * 8 + ((dd >> 3) & 1) * 4
                               + ((ss & 15) >> 3) * 2 + (ss & 1)] = __float2half_rn(val);
                        };
                        vst(s, d, v00);     vst(s, d + 1, v01);
                        vst(s + 8, d, v10); vst(s + 8, d + 1, v11);
                    }
                }
            }
        }
        return;
    }

    #pragma unroll
    for (int mt = 0; mt < 4; mt++) {
        #pragma unroll
        for (int nt = 0; nt < 4; nt++) {
            const int gm = rowBase + wm + mt * 16 + lr;
            const int gn = colBase + wn + nt * 8 + 2 * lc;
            float* a = acc[mt][nt];
            #pragma unroll
            for (int r = 0; r < 2; r++)
                *(float2*)&C[(size_t)(gm + r * 8) * Ntot + gn] =
                    make_float2(a[r * 2 + 0], a[r * 2 + 1]);
        }
    }
}

// ---------------------------------------------------------------------------
// FP16 flash attention, 128-key tiles (two 64-key frag blocks per stage).
// smem: K[2][16384] + V[2][16384] halfs = 128 KB. 1 CTA/SM.
// ---------------------------------------------------------------------------
#define FLASH_SMEM (4 * 16384 * 2)

__global__ void __launch_bounds__(256, 1) flash_kernel(
    const __half* __restrict__ qf, const __half* __restrict__ kf,
    const __half* __restrict__ vf, const float* __restrict__ mask,
    float* __restrict__ ctx, __half* __restrict__ ctxp, float scale)
{
    const int qi = gridDim.x - 1 - blockIdx.x;      // heavy tiles first
    const int rowBase = qi * 128;
    const int bh = blockIdx.y;
    const int b = bh >> 4, h = bh & 15;

    const __half* Kg = kf + (size_t)bh * 32 * 8192;   // 64-key blocks of 8192
    const __half* Vg = vf + (size_t)bh * 32 * 8192;
    const float* mrow = mask + (size_t)b * S_;

    extern __shared__ __half smh[];
    const uint32_t smemU = (uint32_t)__cvta_generic_to_shared(smh);

    const int tx = threadIdx.x;
    const int lane = tx & 31, wid = tx >> 5;
    const int lr = lane >> 2, lc = lane & 3;
    const int r0g = rowBase + wid * 16 + lr;
    const int r1g = r0g + 8;

    // Q fragments: 8 LDG.128
    uint32_t qfr[8][4];
    {
        const __half* Qg = qf + (((size_t)bh * 16 + qi) * 8 + wid) * 2048 + lane * 8;
        #pragma unroll
        for (int ks = 0; ks < 8; ks++) {
            uint4 t = *(const uint4*)(Qg + ks * 256);
            qfr[ks][0] = t.x; qfr[ks][1] = t.y; qfr[ks][2] = t.z; qfr[ks][3] = t.w;
        }
    }

    const int jEnd = qi + 1;    // 128-key tiles
    auto cpKV = [&](int j, int st) {
        const __half* ksrc = Kg + (size_t)j * 16384;
        const __half* vsrc = Vg + (size_t)j * 16384;
        const uint32_t kd = smemU + st * 32768;
        const uint32_t vd = smemU + 65536 + st * 32768;
        #pragma unroll
        for (int i = 0; i < 8; i++) {
            const int i16 = tx + i * 256;
            cp16(kd + i16 * 16, ksrc + i16 * 8);
            cp16(vd + i16 * 16, vsrc + i16 * 8);
        }
    };
    cpKV(0, 0); CP_COMMIT(); CP_WAIT0();
    __syncthreads();

    float oacc[16][4];
    #pragma unroll
    for (int i = 0; i < 16; i++)
        #pragma unroll
        for (int r = 0; r < 4; r++) oacc[i][r] = 0.f;
    float m0 = -1e30f, m1 = -1e30f, l0 = 0.f, l1 = 0.f;

    for (int j = 0; j < jEnd; j++) {
        const int st = j & 1;
        const bool more = (j + 1 < jEnd);
        if (more) { cpKV(j + 1, st ^ 1); CP_COMMIT(); }

        // ---- S = Q @ K^T over 128 keys ----
        float sacc[16][4];
        #pragma unroll
        for (int nt = 0; nt < 16; nt++)
            #pragma unroll
            for (int r = 0; r < 4; r++) sacc[nt][r] = 0.f;

        const __half* kb = smh + st * 16384;
        #pragma unroll
        for (int ks = 0; ks < 8; ks++) {
            #pragma unroll
            for (int np = 0; np < 8; np++) {
                const __half* p = kb + (np >> 2) * 8192 + ks * 1024
                                + (np & 3) * 256 + lane * 8;
                uint4 t = *(const uint4*)p;
                uint32_t b0[2] = { t.x, t.y };
                uint32_t b1[2] = { t.z, t.w };
                mma_f16(sacc[2 * np],     qfr[ks], b0);
                mma_f16(sacc[2 * np + 1], qfr[ks], b1);
            }
        }

        // ---- scale + mask + causal + online softmax ----
        const int keyBase = j * 128;
        float mt0 = -1e30f, mt1 = -1e30f;
        #pragma unroll
        for (int nt = 0; nt < 16; nt++) {
            const int kcol = keyBase + nt * 8 + 2 * lc;
            float2 mk = *(const float2*)&mrow[kcol];
            float s0 = sacc[nt][0] * scale + mk.x;
            float s1 = sacc[nt][1] * scale + mk.y;
            float s2 = sacc[nt][2] * scale + mk.x;
            float s3 = sacc[nt][3] * scale + mk.y;
            if (kcol     > r0g) s0 = -10000.f;
            if (kcol + 1 > r0g) s1 = -10000.f;
            if (kcol     > r1g) s2 = -10000.f;
            if (kcol + 1 > r1g) s3 = -10000.f;
            sacc[nt][0] = s0; sacc[nt][1] = s1; sacc[nt][2] = s2; sacc[nt][3] = s3;
            mt0 = fmaxf(mt0, fmaxf(s0, s1));
            mt1 = fmaxf(mt1, fmaxf(s2, s3));
        }
        mt0 = fmaxf(mt0, __shfl_xor_sync(0xffffffffu, mt0, 1));
        mt0 = fmaxf(mt0, __shfl_xor_sync(0xffffffffu, mt0, 2));
        mt1 = fmaxf(mt1, __shfl_xor_sync(0xffffffffu, mt1, 1));
        mt1 = fmaxf(mt1, __shfl_xor_sync(0xffffffffu, mt1, 2));

        const float mn0 = fmaxf(m0, mt0), mn1 = fmaxf(m1, mt1);
        const float a0 = __expf(m0 - mn0), a1 = __expf(m1 - mn1);
        m0 = mn0; m1 = mn1;

        float ts0 = 0.f, ts1 = 0.f;
        #pragma unroll
        for (int nt = 0; nt < 16; nt++) {
            float p0 = __expf(sacc[nt][0] - mn0);
            float p1 = __expf(sacc[nt][1] - mn0);
            float p2 = __expf(sacc[nt][2] - mn1);
            float p3 = __expf(sacc[nt][3] - mn1);
            sacc[nt][0] = p0; sacc[nt][1] = p1; sacc[nt][2] = p2; sacc[nt][3] = p3;
            ts0 += p0 + p1;
            ts1 += p2 + p3;
        }
        ts0 += __shfl_xor_sync(0xffffffffu, ts0, 1);
        ts0 += __shfl_xor_sync(0xffffffffu, ts0, 2);
        ts1 += __shfl_xor_sync(0xffffffffu, ts1, 1);
        ts1 += __shfl_xor_sync(0xffffffffu, ts1, 2);
        l0 = l0 * a0 + ts0;
        l1 = l1 * a1 + ts1;

        #pragma unroll
        for (int nt = 0; nt < 16; nt++) {
            oacc[nt][0] *= a0; oacc[nt][1] *= a0;
            oacc[nt][2] *= a1; oacc[nt][3] *= a1;
        }

        // ---- O += P @ V (P fp16 in-register, 8 k16-steps) ----
        const __half* vb = smh + 32768 + st * 16384;
        #pragma unroll
        for (int ks = 0; ks < 8; ks++) {
            uint32_t af[4];
            af[0] = h2u(__floats2half2_rn(sacc[2 * ks][0],     sacc[2 * ks][1]));
            af[1] = h2u(__floats2half2_rn(sacc[2 * ks][2],     sacc[2 * ks][3]));
            af[2] = h2u(__floats2half2_rn(sacc[2 * ks + 1][0], sacc[2 * ks + 1][1]));
            af[3] = h2u(__floats2half2_rn(sacc[2 * ks + 1][2], sacc[2 * ks + 1][3]));
            const __half* vt = vb + (ks >> 2) * 8192 + (ks & 3) * 2048;
            #pragma unroll
            for (int np = 0; np < 8; np++) {
                uint4 t = *(const uint4*)(vt + np * 256 + lane * 8);
                uint32_t b0[2] = { t.x, t.y };
                uint32_t b1[2] = { t.z, t.w };
                mma_f16(oacc[2 * np],     af, b0);
                mma_f16(oacc[2 * np + 1], af, b1);
            }
        }

        if (more) { CP_WAIT0(); __syncthreads(); }
    }

    // ---- epilogue: exact ctx [B,S,H] + fp16 GEMM-A-frag copy ----
    const float inv0 = 1.0f / l0;
    const float inv1 = 1.0f / l1;
    const size_t o0 = ((size_t)b * S_ + r0g) * H_ + h * 128 + 2 * lc;
    const size_t o1 = ((size_t)b * S_ + r1g) * H_ + h * 128 + 2 * lc;
    const int mg = b * S_ + r0g;
    #pragma unroll
    for (int nt = 0; nt < 16; nt++) {
        float v0 = oacc[nt][0] * inv0, v1 = oacc[nt][1] * inv0;
        float v2 = oacc[nt][2] * inv1, v3 = oacc[nt][3] * inv1;
        *(float2*)(ctx + o0 + nt * 8) = make_float2(v0, v1);
        *(float2*)(ctx + o1 + nt * 8) = make_float2(v2, v3);
        const int k0 = h * 128 + nt * 8 + 2 * lc;
        __half2 h01 = __floats2half2_rn(v0, v1);
        __half2 h23 = __floats2half2_rn(v2, v3);
        uint2 u = make_uint2(h2u(h01), h2u(h23));
        *(uint2*)&ctxp[afragH(mg, k0)] = u;
    }
}

// ---------------------------------------------------------------------------
extern "C" void kernel_launch(void* const* d_in, const int* in_sizes, int n_in,
                              void* d_out, int out_size)
{
    const float* x    = (const float*)d_in[0];
    const float* mask = (const float*)d_in[1];
    const float* qkvw = (const float*)d_in[2];
    const float* qkvb = (const float*)d_in[3];
    const float* ow   = (const float*)d_in[4];
    const float* nw   = (const float*)d_in[5];
    const float* nb   = (const float*)d_in[6];

    float* out     = (float*)d_out;
    float* out_o   = out;
    float* out_k   = out + 1 * BSH;
    float* out_v   = out + 2 * BSH;
    float* out_ctx = out + 3 * BSH;
    float* out_ln  = out + 4 * BSH;

    __half *qfr, *kfr, *vfr, *lnp, *ctxp, *qkvwP, *owP;
    cudaGetSymbolAddress((void**)&qfr,   g_qfr);
    cudaGetSymbolAddress((void**)&kfr,   g_kfr);
    cudaGetSymbolAddress((void**)&vfr,   g_vfr);
    cudaGetSymbolAddress((void**)&lnp,   g_lnp);
    cudaGetSymbolAddress((void**)&ctxp,  g_ctxp);
    cudaGetSymbolAddress((void**)&qkvwP, g_qkvwP);
    cudaGetSymbolAddress((void**)&owP,   g_owP);

    cudaFuncSetAttribute(mma_gemm2<3>, cudaFuncAttributeMaxDynamicSharedMemorySize, GEMM_SMEM);
    cudaFuncSetAttribute(mma_gemm2<0>, cudaFuncAttributeMaxDynamicSharedMemorySize, GEMM_SMEM);
    cudaFuncSetAttribute(flash_kernel, cudaFuncAttributeMaxDynamicSharedMemorySize, FLASH_SMEM);

    const float scale = 1.0f / sqrtf((float)DH);

    prep_b<<<dim3(KT_A, 3 * H_ / 32), 256>>>(qkvw, qkvwP, 3 * H_);
    prep_b<<<dim3(KT_A, H_ / 32), 256>>>(ow, owP, H_);

    ln_kernel<<<B_ * S_, 256>>>(x, nw, nb, out_ln, lnp);

    mma_gemm2<3><<<dim3(48, 32), 256, GEMM_SMEM>>>(
        lnp, qkvwP, nullptr, qfr, out_k, out_v, kfr, vfr, qkvb, 3 * H_);

    flash_kernel<<<dim3(16, BH), 256, FLASH_SMEM>>>(
        qfr, kfr, vfr, mask, out_ctx, ctxp, scale);

    mma_gemm2<0><<<dim3(16, 32), 256, GEMM_SMEM>>>(
        ctxp, owP, out_o, nullptr, nullptr, nullptr, nullptr, nullptr, nullptr, H_);
}

// round 15
// speedup vs baseline: 1.1737x; 1.0280x over previous
#include <cuda_runtime.h>
#include <cuda_fp16.h>
#include <cstdint>
#include <math.h>

#define B_    2
#define S_    2048
#define H_    2048
#define HEADS 16
#define DH    128
#define BH    (B_*HEADS)
#define BSH   ((size_t)B_*S_*H_)
#define KT_A  64

// ---------------------------------------------------------------------------
__device__ __half g_qfr[BSH];                    // Q flash-A-frags fp16
__device__ __half g_kfr[BSH];                    // K flash-B-frags fp16
__device__ __half g_vfr[BSH];                    // V flash-B-frags fp16
__device__ __half g_lnp[BSH];                    // LN out, GEMM-A-frag fp16
__device__ __half g_ctxp[BSH];                   // ctx,    GEMM-A-frag fp16
__device__ __half g_qkvwP[(size_t)3*H_*H_];      // qkvw, B-frag fp16
__device__ __half g_owP[(size_t)H_*H_];          // ow,   B-frag fp16

// ---------------------------------------------------------------------------
__device__ __forceinline__ uint32_t h2u(__half2 h) { return *(uint32_t*)&h; }
__device__ __forceinline__ void mma_f16(float* c, const uint32_t* a, const uint32_t* b) {
    asm volatile(
        "mma.sync.aligned.m16n8k16.row.col.f32.f16.f16.f32 "
        "{%0,%1,%2,%3},{%4,%5,%6,%7},{%8,%9},{%0,%1,%2,%3};\n"
        : "+f"(c[0]), "+f"(c[1]), "+f"(c[2]), "+f"(c[3])
        : "r"(a[0]), "r"(a[1]), "r"(a[2]), "r"(a[3]), "r"(b[0]), "r"(b[1]));
}
__device__ __forceinline__ void cp16(uint32_t dst, const void* src) {
    asm volatile("cp.async.cg.shared.global [%0], [%1], 16;\n" :: "r"(dst), "l"(src));
}
#define CP_COMMIT() asm volatile("cp.async.commit_group;\n")
#define CP_WAIT0()  asm volatile("cp.async.wait_group 0;\n")
#define CP_WAIT1()  asm volatile("cp.async.wait_group 1;\n")

// fp16 GEMM A-fragment index (m16n8k16), K=2048
__device__ __forceinline__ size_t afragH(int m, int k) {
    return ((size_t)((m >> 4) * KT_A + (k >> 5))) * 512
         + (((k >> 4) & 1) * 256)
         + (((m & 7) * 4 + ((k >> 1) & 3)) * 8)
         + ((((k >> 3) & 1) * 2 + ((m >> 3) & 1)) * 2)
         + (k & 1);
}

// ---------------------------------------------------------------------------
// Weight prep (both weights in one launch):
// blockIdx.y < 192 -> qkvw (N=6144), else -> ow (N=2048, n32 = y-192)
// ---------------------------------------------------------------------------
__global__ void __launch_bounds__(256) prep_b2(
    const float* __restrict__ wq, __half* __restrict__ outq,
    const float* __restrict__ wo, __half* __restrict__ outo)
{
    const int kt = blockIdx.x;
    int n32 = blockIdx.y;
    const float* w;
    __half* out;
    int N;
    if (n32 < 192) { w = wq; out = outq; N = 3 * H_; }
    else           { w = wo; out = outo; N = H_; n32 -= 192; }

    __shared__ float sm[32][33];
    const int tx = threadIdx.x;
    const int kl = tx >> 5, nl = tx & 31;
    #pragma unroll
    for (int i = 0; i < 32; i += 8)
        sm[kl + i][nl] = w[(size_t)(kt * 32 + kl + i) * N + n32 * 32 + nl];
    __syncthreads();
    const size_t base = ((size_t)n32 * KT_A + kt) * 1024;
    #pragma unroll
    for (int e = tx; e < 1024; e += 256) {
        const int k = e >> 5, n = e & 31;
        const int off = ((k >> 4) * 512) + (((k >> 3) & 1) * 256)
                      + (((n & 7) * 4 + ((k >> 1) & 3)) * 8)
                      + ((n >> 3) * 2) + (k & 1);
        out[base + off] = __float2half_rn(sm[k][n]);
    }
}

// ---------------------------------------------------------------------------
// LayerNorm: exact y + fp16 GEMM-A-frag copy
// ---------------------------------------------------------------------------
__global__ void __launch_bounds__(256) ln_kernel(
    const float* __restrict__ x, const float* __restrict__ g,
    const float* __restrict__ b, float* __restrict__ y, __half* __restrict__ yp)
{
    const int row = blockIdx.x;
    const float* xr = x + (size_t)row * H_;
    float s = 0.f, ss = 0.f;
    for (int i = threadIdx.x; i < H_; i += 256) {
        float t = xr[i];
        s += t; ss += t * t;
    }
    #pragma unroll
    for (int o = 16; o; o >>= 1) {
        s  += __shfl_xor_sync(0xffffffffu, s,  o);
        ss += __shfl_xor_sync(0xffffffffu, ss, o);
    }
    __shared__ float red[2][8];
    const int w = threadIdx.x >> 5, l = threadIdx.x & 31;
    if (l == 0) { red[0][w] = s; red[1][w] = ss; }
    __syncthreads();
    __shared__ float stats[2];
    if (threadIdx.x == 0) {
        float S = 0.f, SS = 0.f;
        #pragma unroll
        for (int i = 0; i < 8; i++) { S += red[0][i]; SS += red[1][i]; }
        float mu  = S / (float)H_;
        float var = SS / (float)H_ - mu * mu;
        stats[0] = mu;
        stats[1] = rsqrtf(var + 1e-12f);
    }
    __syncthreads();
    const float mu = stats[0], rstd = stats[1];
    float* yr = y + (size_t)row * H_;
    for (int i = threadIdx.x; i < H_; i += 256) {
        float v = (xr[i] - mu) * rstd * g[i] + b[i];
        yr[i] = v;
        yp[afragH(row, i)] = __float2half_rn(v);
    }
}

// ---------------------------------------------------------------------------
// FP16 mma.sync GEMM: CTA 64x128, 8 warps (2Mx4N, warp tile 32x32),
// K-slab 64 per stage, 3 stages, 3 CTAs/SM (24 warps/SM).
// EPI: 0 plain C; 3 QKV scatter (flash frags + exact k/v + bias).
// ---------------------------------------------------------------------------
#define STG_HALFS 12288                   // A 4096 + B 8192 halfs = 24 KB
#define GEMM_SMEM (3 * STG_HALFS * 2)     // 73728 B

template<int EPI>
__global__ void __launch_bounds__(256, 3) mma_gemm2(
    const __half* __restrict__ Ap, const __half* __restrict__ Bp,
    float* __restrict__ C,
    __half* __restrict__ Qf, float* __restrict__ Ck, float* __restrict__ Cv,
    __half* __restrict__ Kf, __half* __restrict__ Vf,
    const float* __restrict__ bias, int Ntot)
{
    const int m16g0 = blockIdx.y * 4;
    const int n32g0 = blockIdx.x * 4;
    const int rowBase = blockIdx.y * 64;
    const int colBase = blockIdx.x * 128;

    extern __shared__ __half smh[];
    const uint32_t smemU = (uint32_t)__cvta_generic_to_shared(smh);

    const int tx = threadIdx.x;
    const int lane = tx & 31, warp = tx >> 5;
    const int wm = (warp >> 2) * 32;   // 0 or 32
    const int wn = (warp & 3) * 32;    // 0..96
    const int lr = lane >> 2;
    const int lc = lane & 3;

    // Stage = K-slab 64: A 4 m16 chunks x 1024 halfs, B 4 n32 chunks x 2048
    auto loadStage = [&](int t, int st) {
        const uint32_t sbase = smemU + st * STG_HALFS * 2;
        #pragma unroll
        for (int i = 0; i < 6; i++) {
            const int idx = tx + i * 256;          // uint4 index 0..1535
            if (idx < 512) {                        // A: 4 chunks x 128 uint4
                const int g = idx >> 7, rem = idx & 127;
                cp16(sbase + idx * 16,
                     Ap + ((size_t)(m16g0 + g) * KT_A + 2 * t) * 512 + rem * 8);
            } else {                                // B: 4 chunks x 256 uint4
                const int j = idx - 512;
                const int nb = j >> 8, rem = j & 255;
                cp16(sbase + idx * 16,
                     Bp + ((size_t)(n32g0 + nb) * KT_A + 2 * t) * 1024 + rem * 8);
            }
        }
    };

    float acc[2][4][4];
    #pragma unroll
    for (int i = 0; i < 2; i++)
        #pragma unroll
        for (int j = 0; j < 4; j++)
            #pragma unroll
            for (int r = 0; r < 4; r++) acc[i][j][r] = 0.f;

    loadStage(0, 0); CP_COMMIT();
    loadStage(1, 1); CP_COMMIT();

    const int T = KT_A / 2;   // 32 stages
    for (int t = 0; t < T; t++) {
        const int st = t % 3;
        CP_WAIT1();
        __syncthreads();
        if (t + 2 < T) { loadStage(t + 2, (t + 2) % 3); CP_COMMIT(); }

        const __half* sf = smh + st * STG_HALFS;
        const __half* aB = sf + (warp >> 2) * 2048;          // 2 m16-chunks
        const __half* bB = sf + 4096 + (warp & 3) * 2048;    // 1 n32-chunk

        #pragma unroll
        for (int sub = 0; sub < 2; sub++) {
            #pragma unroll
            for (int ks = 0; ks < 2; ks++) {
                uint32_t af[2][4];
                #pragma unroll
                for (int mt = 0; mt < 2; mt++) {
                    uint4 v = *(const uint4*)(aB + mt * 1024 + sub * 512
                                              + ks * 256 + lane * 8);
                    af[mt][0] = v.x; af[mt][1] = v.y; af[mt][2] = v.z; af[mt][3] = v.w;
                }
                uint4 tb0 = *(const uint4*)(bB + sub * 1024 + ks * 512 + lane * 8);
                uint4 tb1 = *(const uint4*)(bB + sub * 1024 + ks * 512 + 256 + lane * 8);
                uint32_t bf[4][2];
                bf[0][0] = tb0.x; bf[0][1] = tb1.x;
                bf[1][0] = tb0.y; bf[1][1] = tb1.y;
                bf[2][0] = tb0.z; bf[2][1] = tb1.z;
                bf[3][0] = tb0.w; bf[3][1] = tb1.w;
                #pragma unroll
                for (int mt = 0; mt < 2; mt++)
                    #pragma unroll
                    for (int nt = 0; nt < 4; nt++)
                        mma_f16(acc[mt][nt], af[mt], bf[nt]);
            }
        }
    }

    if (EPI == 3) {
        const int whichBlk = colBase >> 11;
        const int h = (colBase & 2047) >> 7;
        #pragma unroll
        for (int mt = 0; mt < 2; mt++) {
            #pragma unroll
            for (int nt = 0; nt < 4; nt++) {
                const int gn = colBase + wn + nt * 8 + 2 * lc;
                const int d  = gn & 127;
                const int m0 = rowBase + wm + mt * 16 + lr;
                const int b  = m0 >> 11, s = m0 & 2047;
                float* a = acc[mt][nt];
                const float v00 = a[0] + bias[gn], v01 = a[1] + bias[gn + 1];
                const float v10 = a[2] + bias[gn], v11 = a[3] + bias[gn + 1];
                if (whichBlk == 0) {
                    __half* qp = Qf
                        + (((((size_t)(b * 16 + h) * 16 + (s >> 7)) * 8 + ((s >> 4) & 7)) * 8
                            + (d >> 4)) * 256) + lane * 8 + ((d >> 3) & 1) * 4;
                    *(__half2*)(qp)     = __floats2half2_rn(v00, v01);
                    *(__half2*)(qp + 2) = __floats2half2_rn(v10, v11);
                } else {
                    float* base = (whichBlk == 1) ? Ck : Cv;
                    *(float2*)&base[((((size_t)b * 16 + h) << 11) + s) * 128 + d] =
                        make_float2(v00, v01);
                    *(float2*)&base[((((size_t)b * 16 + h) << 11) + s + 8) * 128 + d] =
                        make_float2(v10, v11);
                    if (whichBlk == 1) {
                        __half* kb = Kf + (((size_t)(b * 16 + h) * 32) + (s >> 6)) * 8192
                                   + (d >> 4) * 1024 + lane * 8 + ((d >> 3) & 1) * 2;
                        const int nt0 = (s & 63) >> 3;
                        *(__half2*)(kb + (nt0 >> 1) * 256 + (nt0 & 1) * 4) =
                            __floats2half2_rn(v00, v01);
                        const int nt1 = nt0 + 1;
                        *(__half2*)(kb + (nt1 >> 1) * 256 + (nt1 & 1) * 4) =
                            __floats2half2_rn(v10, v11);
                    } else {
                        const size_t vblk =
                            (((size_t)(b * 16 + h) * 32) + (s >> 6)) * 8192
                            + ((s & 63) >> 4) * 2048 + (d >> 4) * 256;
                        auto vst = [&](int ss, int dd, float val) {
                            const int la = (dd & 7) * 4 + ((ss >> 1) & 3);
                            Vf[vblk + la * 8 + ((dd >> 3) & 1) * 4
                               + ((ss & 15) >> 3) * 2 + (ss & 1)] = __float2half_rn(val);
                        };
                        vst(s, d, v00);     vst(s, d + 1, v01);
                        vst(s + 8, d, v10); vst(s + 8, d + 1, v11);
                    }
                }
            }
        }
        return;
    }

    #pragma unroll
    for (int mt = 0; mt < 2; mt++) {
        #pragma unroll
        for (int nt = 0; nt < 4; nt++) {
            const int gm = rowBase + wm + mt * 16 + lr;
            const int gn = colBase + wn + nt * 8 + 2 * lc;
            float* a = acc[mt][nt];
            #pragma unroll
            for (int r = 0; r < 2; r++)
                *(float2*)&C[(size_t)(gm + r * 8) * Ntot + gn] =
                    make_float2(a[r * 2 + 0], a[r * 2 + 1]);
        }
    }
}

// ---------------------------------------------------------------------------
// FP16 flash attention, 128-key tiles (unchanged from R14)
// ---------------------------------------------------------------------------
#define FLASH_SMEM (4 * 16384 * 2)

__global__ void __launch_bounds__(256, 1) flash_kernel(
    const __half* __restrict__ qf, const __half* __restrict__ kf,
    const __half* __restrict__ vf, const float* __restrict__ mask,
    float* __restrict__ ctx, __half* __restrict__ ctxp, float scale)
{
    const int qi = gridDim.x - 1 - blockIdx.x;
    const int rowBase = qi * 128;
    const int bh = blockIdx.y;
    const int b = bh >> 4, h = bh & 15;

    const __half* Kg = kf + (size_t)bh * 32 * 8192;
    const __half* Vg = vf + (size_t)bh * 32 * 8192;
    const float* mrow = mask + (size_t)b * S_;

    extern __shared__ __half smh[];
    const uint32_t smemU = (uint32_t)__cvta_generic_to_shared(smh);

    const int tx = threadIdx.x;
    const int lane = tx & 31, wid = tx >> 5;
    const int lr = lane >> 2, lc = lane & 3;
    const int r0g = rowBase + wid * 16 + lr;
    const int r1g = r0g + 8;

    uint32_t qfr[8][4];
    {
        const __half* Qg = qf + (((size_t)bh * 16 + qi) * 8 + wid) * 2048 + lane * 8;
        #pragma unroll
        for (int ks = 0; ks < 8; ks++) {
            uint4 t = *(const uint4*)(Qg + ks * 256);
            qfr[ks][0] = t.x; qfr[ks][1] = t.y; qfr[ks][2] = t.z; qfr[ks][3] = t.w;
        }
    }

    const int jEnd = qi + 1;
    auto cpKV = [&](int j, int st) {
        const __half* ksrc = Kg + (size_t)j * 16384;
        const __half* vsrc = Vg + (size_t)j * 16384;
        const uint32_t kd = smemU + st * 32768;
        const uint32_t vd = smemU + 65536 + st * 32768;
        #pragma unroll
        for (int i = 0; i < 8; i++) {
            const int i16 = tx + i * 256;
            cp16(kd + i16 * 16, ksrc + i16 * 8);
            cp16(vd + i16 * 16, vsrc + i16 * 8);
        }
    };
    cpKV(0, 0); CP_COMMIT(); CP_WAIT0();
    __syncthreads();

    float oacc[16][4];
    #pragma unroll
    for (int i = 0; i < 16; i++)
        #pragma unroll
        for (int r = 0; r < 4; r++) oacc[i][r] = 0.f;
    float m0 = -1e30f, m1 = -1e30f, l0 = 0.f, l1 = 0.f;

    for (int j = 0; j < jEnd; j++) {
        const int st = j & 1;
        const bool more = (j + 1 < jEnd);
        if (more) { cpKV(j + 1, st ^ 1); CP_COMMIT(); }

        float sacc[16][4];
        #pragma unroll
        for (int nt = 0; nt < 16; nt++)
            #pragma unroll
            for (int r = 0; r < 4; r++) sacc[nt][r] = 0.f;

        const __half* kb = smh + st * 16384;
        #pragma unroll
        for (int ks = 0; ks < 8; ks++) {
            #pragma unroll
            for (int np = 0; np < 8; np++) {
                const __half* p = kb + (np >> 2) * 8192 + ks * 1024
                                + (np & 3) * 256 + lane * 8;
                uint4 t = *(const uint4*)p;
                uint32_t b0[2] = { t.x, t.y };
                uint32_t b1[2] = { t.z, t.w };
                mma_f16(sacc[2 * np],     qfr[ks], b0);
                mma_f16(sacc[2 * np + 1], qfr[ks], b1);
            }
        }

        const int keyBase = j * 128;
        float mt0 = -1e30f, mt1 = -1e30f;
        #pragma unroll
        for (int nt = 0; nt < 16; nt++) {
            const int kcol = keyBase + nt * 8 + 2 * lc;
            float2 mk = *(const float2*)&mrow[kcol];
            float s0 = sacc[nt][0] * scale + mk.x;
            float s1 = sacc[nt][1] * scale + mk.y;
            float s2 = sacc[nt][2] * scale + mk.x;
            float s3 = sacc[nt][3] * scale + mk.y;
            if (kcol     > r0g) s0 = -10000.f;
            if (kcol + 1 > r0g) s1 = -10000.f;
            if (kcol     > r1g) s2 = -10000.f;
            if (kcol + 1 > r1g) s3 = -10000.f;
            sacc[nt][0] = s0; sacc[nt][1] = s1; sacc[nt][2] = s2; sacc[nt][3] = s3;
            mt0 = fmaxf(mt0, fmaxf(s0, s1));
            mt1 = fmaxf(mt1, fmaxf(s2, s3));
        }
        mt0 = fmaxf(mt0, __shfl_xor_sync(0xffffffffu, mt0, 1));
        mt0 = fmaxf(mt0, __shfl_xor_sync(0xffffffffu, mt0, 2));
        mt1 = fmaxf(mt1, __shfl_xor_sync(0xffffffffu, mt1, 1));
        mt1 = fmaxf(mt1, __shfl_xor_sync(0xffffffffu, mt1, 2));

        const float mn0 = fmaxf(m0, mt0), mn1 = fmaxf(m1, mt1);
        const float a0 = __expf(m0 - mn0), a1 = __expf(m1 - mn1);
        m0 = mn0; m1 = mn1;

        float ts0 = 0.f, ts1 = 0.f;
        #pragma unroll
        for (int nt = 0; nt < 16; nt++) {
            float p0 = __expf(sacc[nt][0] - mn0);
            float p1 = __expf(sacc[nt][1] - mn0);
            float p2 = __expf(sacc[nt][2] - mn1);
            float p3 = __expf(sacc[nt][3] - mn1);
            sacc[nt][0] = p0; sacc[nt][1] = p1; sacc[nt][2] = p2; sacc[nt][3] = p3;
            ts0 += p0 + p1;
            ts1 += p2 + p3;
        }
        ts0 += __shfl_xor_sync(0xffffffffu, ts0, 1);
        ts0 += __shfl_xor_sync(0xffffffffu, ts0, 2);
        ts1 += __shfl_xor_sync(0xffffffffu, ts1, 1);
        ts1 += __shfl_xor_sync(0xffffffffu, ts1, 2);
        l0 = l0 * a0 + ts0;
        l1 = l1 * a1 + ts1;

        #pragma unroll
        for (int nt = 0; nt < 16; nt++) {
            oacc[nt][0] *= a0; oacc[nt][1] *= a0;
            oacc[nt][2] *= a1; oacc[nt][3] *= a1;
        }

        const __half* vb = smh + 32768 + st * 16384;
        #pragma unroll
        for (int ks = 0; ks < 8; ks++) {
            uint32_t af[4];
            af[0] = h2u(__floats2half2_rn(sacc[2 * ks][0],     sacc[2 * ks][1]));
            af[1] = h2u(__floats2half2_rn(sacc[2 * ks][2],     sacc[2 * ks][3]));
            af[2] = h2u(__floats2half2_rn(sacc[2 * ks + 1][0], sacc[2 * ks + 1][1]));
            af[3] = h2u(__floats2half2_rn(sacc[2 * ks + 1][2], sacc[2 * ks + 1][3]));
            const __half* vt = vb + (ks >> 2) * 8192 + (ks & 3) * 2048;
            #pragma unroll
            for (int np = 0; np < 8; np++) {
                uint4 t = *(const uint4*)(vt + np * 256 + lane * 8);
                uint32_t b0[2] = { t.x, t.y };
                uint32_t b1[2] = { t.z, t.w };
                mma_f16(oacc[2 * np],     af, b0);
                mma_f16(oacc[2 * np + 1], af, b1);
            }
        }

        if (more) { CP_WAIT0(); __syncthreads(); }
    }

    const float inv0 = 1.0f / l0;
    const float inv1 = 1.0f / l1;
    const size_t o0 = ((size_t)b * S_ + r0g) * H_ + h * 128 + 2 * lc;
    const size_t o1 = ((size_t)b * S_ + r1g) * H_ + h * 128 + 2 * lc;
    const int mg = b * S_ + r0g;
    #pragma unroll
    for (int nt = 0; nt < 16; nt++) {
        float v0 = oacc[nt][0] * inv0, v1 = oacc[nt][1] * inv0;
        float v2 = oacc[nt][2] * inv1, v3 = oacc[nt][3] * inv1;
        *(float2*)(ctx + o0 + nt * 8) = make_float2(v0, v1);
        *(float2*)(ctx + o1 + nt * 8) = make_float2(v2, v3);
        const int k0 = h * 128 + nt * 8 + 2 * lc;
        __half2 h01 = __floats2half2_rn(v0, v1);
        __half2 h23 = __floats2half2_rn(v2, v3);
        uint2 u = make_uint2(h2u(h01), h2u(h23));
        *(uint2*)&ctxp[afragH(mg, k0)] = u;
    }
}

// ---------------------------------------------------------------------------
extern "C" void kernel_launch(void* const* d_in, const int* in_sizes, int n_in,
                              void* d_out, int out_size)
{
    const float* x    = (const float*)d_in[0];
    const float* mask = (const float*)d_in[1];
    const float* qkvw = (const float*)d_in[2];
    const float* qkvb = (const float*)d_in[3];
    const float* ow   = (const float*)d_in[4];
    const float* nw   = (const float*)d_in[5];
    const float* nb   = (const float*)d_in[6];

    float* out     = (float*)d_out;
    float* out_o   = out;
    float* out_k   = out + 1 * BSH;
    float* out_v   = out + 2 * BSH;
    float* out_ctx = out + 3 * BSH;
    float* out_ln  = out + 4 * BSH;

    __half *qfr, *kfr, *vfr, *lnp, *ctxp, *qkvwP, *owP;
    cudaGetSymbolAddress((void**)&qfr,   g_qfr);
    cudaGetSymbolAddress((void**)&kfr,   g_kfr);
    cudaGetSymbolAddress((void**)&vfr,   g_vfr);
    cudaGetSymbolAddress((void**)&lnp,   g_lnp);
    cudaGetSymbolAddress((void**)&ctxp,  g_ctxp);
    cudaGetSymbolAddress((void**)&qkvwP, g_qkvwP);
    cudaGetSymbolAddress((void**)&owP,   g_owP);

    cudaFuncSetAttribute(mma_gemm2<3>, cudaFuncAttributeMaxDynamicSharedMemorySize, GEMM_SMEM);
    cudaFuncSetAttribute(mma_gemm2<0>, cudaFuncAttributeMaxDynamicSharedMemorySize, GEMM_SMEM);
    cudaFuncSetAttribute(flash_kernel, cudaFuncAttributeMaxDynamicSharedMemorySize, FLASH_SMEM);

    const float scale = 1.0f / sqrtf((float)DH);

    // 0. Weight prep (both weights, one launch)
    prep_b2<<<dim3(KT_A, 256), 256>>>(qkvw, qkvwP, ow, owP);

    // 1. LayerNorm
    ln_kernel<<<B_ * S_, 256>>>(x, nw, nb, out_ln, lnp);

    // 2. QKV GEMM + scatter (CTA 64x128 -> grid 48 x 64)
    mma_gemm2<3><<<dim3(48, 64), 256, GEMM_SMEM>>>(
        lnp, qkvwP, nullptr, qfr, out_k, out_v, kfr, vfr, qkvb, 3 * H_);

    // 3. Flash attention
    flash_kernel<<<dim3(16, BH), 256, FLASH_SMEM>>>(
        qfr, kfr, vfr, mask, out_ctx, ctxp, scale);

    // 4. Output projection (grid 16 x 64)
    mma_gemm2<0><<<dim3(16, 64), 256, GEMM_SMEM>>>(
        ctxp, owP, out_o, nullptr, nullptr, nullptr, nullptr, nullptr, nullptr, H_);
}

// round 16
// speedup vs baseline: 1.1798x; 1.0052x over previous
#include <cuda_runtime.h>
#include <cuda_fp16.h>
#include <cstdint>
#include <math.h>

#define B_    2
#define S_    2048
#define H_    2048
#define HEADS 16
#define DH    128
#define BH    (B_*HEADS)
#define BSH   ((size_t)B_*S_*H_)
#define KT_A  64

// ---------------------------------------------------------------------------
__device__ __half g_qfr[BSH];                    // Q flash-A-frags fp16 (pre-scaled)
__device__ __half g_kfr[BSH];                    // K flash-B-frags fp16
__device__ __half g_vfr[BSH];                    // V flash-B-frags fp16
__device__ __half g_lnp[BSH];                    // LN out, GEMM-A-frag fp16
__device__ __half g_ctxp[BSH];                   // ctx,    GEMM-A-frag fp16
__device__ __half g_qkvwP[(size_t)3*H_*H_];      // qkvw, B-frag fp16
__device__ __half g_owP[(size_t)H_*H_];          // ow,   B-frag fp16

// ---------------------------------------------------------------------------
__device__ __forceinline__ uint32_t h2u(__half2 h) { return *(uint32_t*)&h; }
__device__ __forceinline__ void mma_f16(float* c, const uint32_t* a, const uint32_t* b) {
    asm volatile(
        "mma.sync.aligned.m16n8k16.row.col.f32.f16.f16.f32 "
        "{%0,%1,%2,%3},{%4,%5,%6,%7},{%8,%9},{%0,%1,%2,%3};\n"
        : "+f"(c[0]), "+f"(c[1]), "+f"(c[2]), "+f"(c[3])
        : "r"(a[0]), "r"(a[1]), "r"(a[2]), "r"(a[3]), "r"(b[0]), "r"(b[1]));
}
__device__ __forceinline__ void cp16(uint32_t dst, const void* src) {
    asm volatile("cp.async.cg.shared.global [%0], [%1], 16;\n" :: "r"(dst), "l"(src));
}
#define CP_COMMIT() asm volatile("cp.async.commit_group;\n")
#define CP_WAIT0()  asm volatile("cp.async.wait_group 0;\n")
#define CP_WAIT1()  asm volatile("cp.async.wait_group 1;\n")

// fp16 GEMM A-fragment index (m16n8k16), K=2048
__device__ __forceinline__ size_t afragH(int m, int k) {
    return ((size_t)((m >> 4) * KT_A + (k >> 5))) * 512
         + (((k >> 4) & 1) * 256)
         + (((m & 7) * 4 + ((k >> 1) & 3)) * 8)
         + ((((k >> 3) & 1) * 2 + ((m >> 3) & 1)) * 2)
         + (k & 1);
}

// ---------------------------------------------------------------------------
// Weight prep (both weights in one launch)
// ---------------------------------------------------------------------------
__global__ void __launch_bounds__(256) prep_b2(
    const float* __restrict__ wq, __half* __restrict__ outq,
    const float* __restrict__ wo, __half* __restrict__ outo)
{
    const int kt = blockIdx.x;
    int n32 = blockIdx.y;
    const float* w;
    __half* out;
    int N;
    if (n32 < 192) { w = wq; out = outq; N = 3 * H_; }
    else           { w = wo; out = outo; N = H_; n32 -= 192; }

    __shared__ float sm[32][33];
    const int tx = threadIdx.x;
    const int kl = tx >> 5, nl = tx & 31;
    #pragma unroll
    for (int i = 0; i < 32; i += 8)
        sm[kl + i][nl] = w[(size_t)(kt * 32 + kl + i) * N + n32 * 32 + nl];
    __syncthreads();
    const size_t base = ((size_t)n32 * KT_A + kt) * 1024;
    #pragma unroll
    for (int e = tx; e < 1024; e += 256) {
        const int k = e >> 5, n = e & 31;
        const int off = ((k >> 4) * 512) + (((k >> 3) & 1) * 256)
                      + (((n & 7) * 4 + ((k >> 1) & 3)) * 8)
                      + ((n >> 3) * 2) + (k & 1);
        out[base + off] = __float2half_rn(sm[k][n]);
    }
}

// ---------------------------------------------------------------------------
// LayerNorm: exact y + fp16 GEMM-A-frag copy
// ---------------------------------------------------------------------------
__global__ void __launch_bounds__(256) ln_kernel(
    const float* __restrict__ x, const float* __restrict__ g,
    const float* __restrict__ b, float* __restrict__ y, __half* __restrict__ yp)
{
    const int row = blockIdx.x;
    const float* xr = x + (size_t)row * H_;
    float s = 0.f, ss = 0.f;
    for (int i = threadIdx.x; i < H_; i += 256) {
        float t = xr[i];
        s += t; ss += t * t;
    }
    #pragma unroll
    for (int o = 16; o; o >>= 1) {
        s  += __shfl_xor_sync(0xffffffffu, s,  o);
        ss += __shfl_xor_sync(0xffffffffu, ss, o);
    }
    __shared__ float red[2][8];
    const int w = threadIdx.x >> 5, l = threadIdx.x & 31;
    if (l == 0) { red[0][w] = s; red[1][w] = ss; }
    __syncthreads();
    __shared__ float stats[2];
    if (threadIdx.x == 0) {
        float S = 0.f, SS = 0.f;
        #pragma unroll
        for (int i = 0; i < 8; i++) { S += red[0][i]; SS += red[1][i]; }
        float mu  = S / (float)H_;
        float var = SS / (float)H_ - mu * mu;
        stats[0] = mu;
        stats[1] = rsqrtf(var + 1e-12f);
    }
    __syncthreads();
    const float mu = stats[0], rstd = stats[1];
    float* yr = y + (size_t)row * H_;
    for (int i = threadIdx.x; i < H_; i += 256) {
        float v = (xr[i] - mu) * rstd * g[i] + b[i];
        yr[i] = v;
        yp[afragH(row, i)] = __float2half_rn(v);
    }
}

// ---------------------------------------------------------------------------
// FP16 mma.sync GEMM: CTA 64x128, warp tile 32x32, K-slab 64, 3 stages,
// 3 CTAs/SM. EPI 3: Q frags pre-scaled by qscale.
// ---------------------------------------------------------------------------
#define STG_HALFS 12288
#define GEMM_SMEM (3 * STG_HALFS * 2)

template<int EPI>
__global__ void __launch_bounds__(256, 3) mma_gemm2(
    const __half* __restrict__ Ap, const __half* __restrict__ Bp,
    float* __restrict__ C,
    __half* __restrict__ Qf, float* __restrict__ Ck, float* __restrict__ Cv,
    __half* __restrict__ Kf, __half* __restrict__ Vf,
    const float* __restrict__ bias, int Ntot, float qscale)
{
    const int m16g0 = blockIdx.y * 4;
    const int n32g0 = blockIdx.x * 4;
    const int rowBase = blockIdx.y * 64;
    const int colBase = blockIdx.x * 128;

    extern __shared__ __half smh[];
    const uint32_t smemU = (uint32_t)__cvta_generic_to_shared(smh);

    const int tx = threadIdx.x;
    const int lane = tx & 31, warp = tx >> 5;
    const int wm = (warp >> 2) * 32;
    const int wn = (warp & 3) * 32;
    const int lr = lane >> 2;
    const int lc = lane & 3;

    auto loadStage = [&](int t, int st) {
        const uint32_t sbase = smemU + st * STG_HALFS * 2;
        #pragma unroll
        for (int i = 0; i < 6; i++) {
            const int idx = tx + i * 256;
            if (idx < 512) {
                const int g = idx >> 7, rem = idx & 127;
                cp16(sbase + idx * 16,
                     Ap + ((size_t)(m16g0 + g) * KT_A + 2 * t) * 512 + rem * 8);
            } else {
                const int j = idx - 512;
                const int nb = j >> 8, rem = j & 255;
                cp16(sbase + idx * 16,
                     Bp + ((size_t)(n32g0 + nb) * KT_A + 2 * t) * 1024 + rem * 8);
            }
        }
    };

    float acc[2][4][4];
    #pragma unroll
    for (int i = 0; i < 2; i++)
        #pragma unroll
        for (int j = 0; j < 4; j++)
            #pragma unroll
            for (int r = 0; r < 4; r++) acc[i][j][r] = 0.f;

    loadStage(0, 0); CP_COMMIT();
    loadStage(1, 1); CP_COMMIT();

    const int T = KT_A / 2;
    for (int t = 0; t < T; t++) {
        const int st = t % 3;
        CP_WAIT1();
        __syncthreads();
        if (t + 2 < T) { loadStage(t + 2, (t + 2) % 3); CP_COMMIT(); }

        const __half* sf = smh + st * STG_HALFS;
        const __half* aB = sf + (warp >> 2) * 2048;
        const __half* bB = sf + 4096 + (warp & 3) * 2048;

        #pragma unroll
        for (int sub = 0; sub < 2; sub++) {
            #pragma unroll
            for (int ks = 0; ks < 2; ks++) {
                uint32_t af[2][4];
                #pragma unroll
                for (int mt = 0; mt < 2; mt++) {
                    uint4 v = *(const uint4*)(aB + mt * 1024 + sub * 512
                                              + ks * 256 + lane * 8);
                    af[mt][0] = v.x; af[mt][1] = v.y; af[mt][2] = v.z; af[mt][3] = v.w;
                }
                uint4 tb0 = *(const uint4*)(bB + sub * 1024 + ks * 512 + lane * 8);
                uint4 tb1 = *(const uint4*)(bB + sub * 1024 + ks * 512 + 256 + lane * 8);
                uint32_t bf[4][2];
                bf[0][0] = tb0.x; bf[0][1] = tb1.x;
                bf[1][0] = tb0.y; bf[1][1] = tb1.y;
                bf[2][0] = tb0.z; bf[2][1] = tb1.z;
                bf[3][0] = tb0.w; bf[3][1] = tb1.w;
                #pragma unroll
                for (int mt = 0; mt < 2; mt++)
                    #pragma unroll
                    for (int nt = 0; nt < 4; nt++)
                        mma_f16(acc[mt][nt], af[mt], bf[nt]);
            }
        }
    }

    if (EPI == 3) {
        const int whichBlk = colBase >> 11;
        const int h = (colBase & 2047) >> 7;
        #pragma unroll
        for (int mt = 0; mt < 2; mt++) {
            #pragma unroll
            for (int nt = 0; nt < 4; nt++) {
                const int gn = colBase + wn + nt * 8 + 2 * lc;
                const int d  = gn & 127;
                const int m0 = rowBase + wm + mt * 16 + lr;
                const int b  = m0 >> 11, s = m0 & 2047;
                float* a = acc[mt][nt];
                const float v00 = a[0] + bias[gn], v01 = a[1] + bias[gn + 1];
                const float v10 = a[2] + bias[gn], v11 = a[3] + bias[gn + 1];
                if (whichBlk == 0) {
                    __half* qp = Qf
                        + (((((size_t)(b * 16 + h) * 16 + (s >> 7)) * 8 + ((s >> 4) & 7)) * 8
                            + (d >> 4)) * 256) + lane * 8 + ((d >> 3) & 1) * 4;
                    *(__half2*)(qp)     = __floats2half2_rn(v00 * qscale, v01 * qscale);
                    *(__half2*)(qp + 2) = __floats2half2_rn(v10 * qscale, v11 * qscale);
                } else {
                    float* base = (whichBlk == 1) ? Ck : Cv;
                    *(float2*)&base[((((size_t)b * 16 + h) << 11) + s) * 128 + d] =
                        make_float2(v00, v01);
                    *(float2*)&base[((((size_t)b * 16 + h) << 11) + s + 8) * 128 + d] =
                        make_float2(v10, v11);
                    if (whichBlk == 1) {
                        __half* kb = Kf + (((size_t)(b * 16 + h) * 32) + (s >> 6)) * 8192
                                   + (d >> 4) * 1024 + lane * 8 + ((d >> 3) & 1) * 2;
                        const int nt0 = (s & 63) >> 3;
                        *(__half2*)(kb + (nt0 >> 1) * 256 + (nt0 & 1) * 4) =
                            __floats2half2_rn(v00, v01);
                        const int nt1 = nt0 + 1;
                        *(__half2*)(kb + (nt1 >> 1) * 256 + (nt1 & 1) * 4) =
                            __floats2half2_rn(v10, v11);
                    } else {
                        const size_t vblk =
                            (((size_t)(b * 16 + h) * 32) + (s >> 6)) * 8192
                            + ((s & 63) >> 4) * 2048 + (d >> 4) * 256;
                        auto vst = [&](int ss, int dd, float val) {
                            const int la = (dd & 7) * 4 + ((ss >> 1) & 3);
                            Vf[vblk + la * 8 + ((dd >> 3) & 1) * 4
                               + ((ss & 15) >> 3) * 2 + (ss & 1)] = __float2half_rn(val);
                        };
                        vst(s, d, v00);     vst(s, d + 1, v01);
                        vst(s + 8, d, v10); vst(s + 8, d + 1, v11);
                    }
                }
            }
        }
        return;
    }

    #pragma unroll
    for (int mt = 0; mt < 2; mt++) {
        #pragma unroll
        for (int nt = 0; nt < 4; nt++) {
            const int gm = rowBase + wm + mt * 16 + lr;
            const int gn = colBase + wn + nt * 8 + 2 * lc;
            float* a = acc[mt][nt];
            #pragma unroll
            for (int r = 0; r < 2; r++)
                *(float2*)&C[(size_t)(gm + r * 8) * Ntot + gn] =
                    make_float2(a[r * 2 + 0], a[r * 2 + 1]);
        }
    }
}

// ---------------------------------------------------------------------------
// FP16 flash attention, 128-key tiles. Scale pre-folded into Q; causal
// masking applied only on the diagonal tile (warp-uniform branch).
// ---------------------------------------------------------------------------
#define FLASH_SMEM (4 * 16384 * 2)

__global__ void __launch_bounds__(256, 1) flash_kernel(
    const __half* __restrict__ qf, const __half* __restrict__ kf,
    const __half* __restrict__ vf, const float* __restrict__ mask,
    float* __restrict__ ctx, __half* __restrict__ ctxp)
{
    const int qi = gridDim.x - 1 - blockIdx.x;
    const int rowBase = qi * 128;
    const int bh = blockIdx.y;
    const int b = bh >> 4, h = bh & 15;

    const __half* Kg = kf + (size_t)bh * 32 * 8192;
    const __half* Vg = vf + (size_t)bh * 32 * 8192;
    const float* mrow = mask + (size_t)b * S_;

    extern __shared__ __half smh[];
    const uint32_t smemU = (uint32_t)__cvta_generic_to_shared(smh);

    const int tx = threadIdx.x;
    const int lane = tx & 31, wid = tx >> 5;
    const int lr = lane >> 2, lc = lane & 3;
    const int r0g = rowBase + wid * 16 + lr;
    const int r1g = r0g + 8;

    uint32_t qfr[8][4];
    {
        const __half* Qg = qf + (((size_t)bh * 16 + qi) * 8 + wid) * 2048 + lane * 8;
        #pragma unroll
        for (int ks = 0; ks < 8; ks++) {
            uint4 t = *(const uint4*)(Qg + ks * 256);
            qfr[ks][0] = t.x; qfr[ks][1] = t.y; qfr[ks][2] = t.z; qfr[ks][3] = t.w;
        }
    }

    const int jEnd = qi + 1;
    auto cpKV = [&](int j, int st) {
        const __half* ksrc = Kg + (size_t)j * 16384;
        const __half* vsrc = Vg + (size_t)j * 16384;
        const uint32_t kd = smemU + st * 32768;
        const uint32_t vd = smemU + 65536 + st * 32768;
        #pragma unroll
        for (int i = 0; i < 8; i++) {
            const int i16 = tx + i * 256;
            cp16(kd + i16 * 16, ksrc + i16 * 8);
            cp16(vd + i16 * 16, vsrc + i16 * 8);
        }
    };
    cpKV(0, 0); CP_COMMIT(); CP_WAIT0();
    __syncthreads();

    float oacc[16][4];
    #pragma unroll
    for (int i = 0; i < 16; i++)
        #pragma unroll
        for (int r = 0; r < 4; r++) oacc[i][r] = 0.f;
    float m0 = -1e30f, m1 = -1e30f, l0 = 0.f, l1 = 0.f;

    for (int j = 0; j < jEnd; j++) {
        const int st = j & 1;
        const bool more = (j + 1 < jEnd);
        const bool diag = (j == qi);
        if (more) { cpKV(j + 1, st ^ 1); CP_COMMIT(); }

        // ---- S = Q @ K^T (Q pre-scaled) ----
        float sacc[16][4];
        #pragma unroll
        for (int nt = 0; nt < 16; nt++)
            #pragma unroll
            for (int r = 0; r < 4; r++) sacc[nt][r] = 0.f;

        const __half* kb = smh + st * 16384;
        #pragma unroll
        for (int ks = 0; ks < 8; ks++) {
            #pragma unroll
            for (int np = 0; np < 8; np++) {
                const __half* p = kb + (np >> 2) * 8192 + ks * 1024
                                + (np & 3) * 256 + lane * 8;
                uint4 t = *(const uint4*)p;
                uint32_t b0[2] = { t.x, t.y };
                uint32_t b1[2] = { t.z, t.w };
                mma_f16(sacc[2 * np],     qfr[ks], b0);
                mma_f16(sacc[2 * np + 1], qfr[ks], b1);
            }
        }

        // ---- mask + (diagonal-only) causal + online softmax ----
        const int keyBase = j * 128;
        float mt0 = -1e30f, mt1 = -1e30f;
        #pragma unroll
        for (int nt = 0; nt < 16; nt++) {
            const int kcol = keyBase + nt * 8 + 2 * lc;
            float2 mk = *(const float2*)&mrow[kcol];
            float s0 = sacc[nt][0] + mk.x;
            float s1 = sacc[nt][1] + mk.y;
            float s2 = sacc[nt][2] + mk.x;
            float s3 = sacc[nt][3] + mk.y;
            if (diag) {
                if (kcol     > r0g) s0 = -10000.f;
                if (kcol + 1 > r0g) s1 = -10000.f;
                if (kcol     > r1g) s2 = -10000.f;
                if (kcol + 1 > r1g) s3 = -10000.f;
            }
            sacc[nt][0] = s0; sacc[nt][1] = s1; sacc[nt][2] = s2; sacc[nt][3] = s3;
            mt0 = fmaxf(mt0, fmaxf(s0, s1));
            mt1 = fmaxf(mt1, fmaxf(s2, s3));
        }
        mt0 = fmaxf(mt0, __shfl_xor_sync(0xffffffffu, mt0, 1));
        mt0 = fmaxf(mt0, __shfl_xor_sync(0xffffffffu, mt0, 2));
        mt1 = fmaxf(mt1, __shfl_xor_sync(0xffffffffu, mt1, 1));
        mt1 = fmaxf(mt1, __shfl_xor_sync(0xffffffffu, mt1, 2));

        const float mn0 = fmaxf(m0, mt0), mn1 = fmaxf(m1, mt1);
        const float a0 = __expf(m0 - mn0), a1 = __expf(m1 - mn1);
        m0 = mn0; m1 = mn1;

        float ts0 = 0.f, ts1 = 0.f;
        #pragma unroll
        for (int nt = 0; nt < 16; nt++) {
            float p0 = __expf(sacc[nt][0] - mn0);
            float p1 = __expf(sacc[nt][1] - mn0);
            float p2 = __expf(sacc[nt][2] - mn1);
            float p3 = __expf(sacc[nt][3] - mn1);
            sacc[nt][0] = p0; sacc[nt][1] = p1; sacc[nt][2] = p2; sacc[nt][3] = p3;
            ts0 += p0 + p1;
            ts1 += p2 + p3;
        }
        ts0 += __shfl_xor_sync(0xffffffffu, ts0, 1);
        ts0 += __shfl_xor_sync(0xffffffffu, ts0, 2);
        ts1 += __shfl_xor_sync(0xffffffffu, ts1, 1);
        ts1 += __shfl_xor_sync(0xffffffffu, ts1, 2);
        l0 = l0 * a0 + ts0;
        l1 = l1 * a1 + ts1;

        #pragma unroll
        for (int nt = 0; nt < 16; nt++) {
            oacc[nt][0] *= a0; oacc[nt][1] *= a0;
            oacc[nt][2] *= a1; oacc[nt][3] *= a1;
        }

        // ---- O += P @ V ----
        const __half* vb = smh + 32768 + st * 16384;
        #pragma unroll
        for (int ks = 0; ks < 8; ks++) {
            uint32_t af[4];
            af[0] = h2u(__floats2half2_rn(sacc[2 * ks][0],     sacc[2 * ks][1]));
            af[1] = h2u(__floats2half2_rn(sacc[2 * ks][2],     sacc[2 * ks][3]));
            af[2] = h2u(__floats2half2_rn(sacc[2 * ks + 1][0], sacc[2 * ks + 1][1]));
            af[3] = h2u(__floats2half2_rn(sacc[2 * ks + 1][2], sacc[2 * ks + 1][3]));
            const __half* vt = vb + (ks >> 2) * 8192 + (ks & 3) * 2048;
            #pragma unroll
            for (int np = 0; np < 8; np++) {
                uint4 t = *(const uint4*)(vt + np * 256 + lane * 8);
                uint32_t b0[2] = { t.x, t.y };
                uint32_t b1[2] = { t.z, t.w };
                mma_f16(oacc[2 * np],     af, b0);
                mma_f16(oacc[2 * np + 1], af, b1);
            }
        }

        if (more) { CP_WAIT0(); __syncthreads(); }
    }

    const float inv0 = 1.0f / l0;
    const float inv1 = 1.0f / l1;
    const size_t o0 = ((size_t)b * S_ + r0g) * H_ + h * 128 + 2 * lc;
    const size_t o1 = ((size_t)b * S_ + r1g) * H_ + h * 128 + 2 * lc;
    const int mg = b * S_ + r0g;
    #pragma unroll
    for (int nt = 0; nt < 16; nt++) {
        float v0 = oacc[nt][0] * inv0, v1 = oacc[nt][1] * inv0;
        float v2 = oacc[nt][2] * inv1, v3 = oacc[nt][3] * inv1;
        *(float2*)(ctx + o0 + nt * 8) = make_float2(v0, v1);
        *(float2*)(ctx + o1 + nt * 8) = make_float2(v2, v3);
        const int k0 = h * 128 + nt * 8 + 2 * lc;
        __half2 h01 = __floats2half2_rn(v0, v1);
        __half2 h23 = __floats2half2_rn(v2, v3);
        uint2 u = make_uint2(h2u(h01), h2u(h23));
        *(uint2*)&ctxp[afragH(mg, k0)] = u;
    }
}

// ---------------------------------------------------------------------------
extern "C" void kernel_launch(void* const* d_in, const int* in_sizes, int n_in,
                              void* d_out, int out_size)
{
    const float* x    = (const float*)d_in[0];
    const float* mask = (const float*)d_in[1];
    const float* qkvw = (const float*)d_in[2];
    const float* qkvb = (const float*)d_in[3];
    const float* ow   = (const float*)d_in[4];
    const float* nw   = (const float*)d_in[5];
    const float* nb   = (const float*)d_in[6];

    float* out     = (float*)d_out;
    float* out_o   = out;
    float* out_k   = out + 1 * BSH;
    float* out_v   = out + 2 * BSH;
    float* out_ctx = out + 3 * BSH;
    float* out_ln  = out + 4 * BSH;

    __half *qfr, *kfr, *vfr, *lnp, *ctxp, *qkvwP, *owP;
    cudaGetSymbolAddress((void**)&qfr,   g_qfr);
    cudaGetSymbolAddress((void**)&kfr,   g_kfr);
    cudaGetSymbolAddress((void**)&vfr,   g_vfr);
    cudaGetSymbolAddress((void**)&lnp,   g_lnp);
    cudaGetSymbolAddress((void**)&ctxp,  g_ctxp);
    cudaGetSymbolAddress((void**)&qkvwP, g_qkvwP);
    cudaGetSymbolAddress((void**)&owP,   g_owP);

    cudaFuncSetAttribute(mma_gemm2<3>, cudaFuncAttributeMaxDynamicSharedMemorySize, GEMM_SMEM);
    cudaFuncSetAttribute(mma_gemm2<0>, cudaFuncAttributeMaxDynamicSharedMemorySize, GEMM_SMEM);
    cudaFuncSetAttribute(flash_kernel, cudaFuncAttributeMaxDynamicSharedMemorySize, FLASH_SMEM);

    const float scale = 1.0f / sqrtf((float)DH);

    prep_b2<<<dim3(KT_A, 256), 256>>>(qkvw, qkvwP, ow, owP);

    ln_kernel<<<B_ * S_, 256>>>(x, nw, nb, out_ln, lnp);

    mma_gemm2<3><<<dim3(48, 64), 256, GEMM_SMEM>>>(
        lnp, qkvwP, nullptr, qfr, out_k, out_v, kfr, vfr, qkvb, 3 * H_, scale);

    flash_kernel<<<dim3(16, BH), 256, FLASH_SMEM>>>(
        qfr, kfr, vfr, mask, out_ctx, ctxp);

    mma_gemm2<0><<<dim3(16, 64), 256, GEMM_SMEM>>>(
        ctxp, owP, out_o, nullptr, nullptr, nullptr, nullptr, nullptr, nullptr, H_, 1.0f);
}

// round 17
// speedup vs baseline: 1.1970x; 1.0145x over previous
#include <cuda_runtime.h>
#include <cuda_fp16.h>
#include <cstdint>
#include <math.h>

#define B_    2
#define S_    2048
#define H_    2048
#define HEADS 16
#define DH    128
#define BH    (B_*HEADS)
#define BSH   ((size_t)B_*S_*H_)
#define KT_A  64
#define LOG2E 1.4426950408889634f
#define MINF2 (-10000.0f * 1.4426950408889634f)

// ---------------------------------------------------------------------------
__device__ __half g_qfr[BSH];                    // Q flash-A-frags fp16 (scale*log2e folded)
__device__ __half g_kfr[BSH];                    // K flash-B-frags fp16
__device__ __half g_vfr[BSH];                    // V flash-B-frags fp16
__device__ __half g_lnp[BSH];                    // LN out, GEMM-A-frag fp16
__device__ __half g_ctxp[BSH];                   // ctx,    GEMM-A-frag fp16
__device__ __half g_qkvwP[(size_t)3*H_*H_];      // qkvw, B-frag fp16
__device__ __half g_owP[(size_t)H_*H_];          // ow,   B-frag fp16

// ---------------------------------------------------------------------------
__device__ __forceinline__ uint32_t h2u(__half2 h) { return *(uint32_t*)&h; }
__device__ __forceinline__ float ex2f(float x) {
    float r;
    asm("ex2.approx.f32 %0, %1;" : "=f"(r) : "f"(x));
    return r;
}
__device__ __forceinline__ void mma_f16(float* c, const uint32_t* a, const uint32_t* b) {
    asm volatile(
        "mma.sync.aligned.m16n8k16.row.col.f32.f16.f16.f32 "
        "{%0,%1,%2,%3},{%4,%5,%6,%7},{%8,%9},{%0,%1,%2,%3};\n"
        : "+f"(c[0]), "+f"(c[1]), "+f"(c[2]), "+f"(c[3])
        : "r"(a[0]), "r"(a[1]), "r"(a[2]), "r"(a[3]), "r"(b[0]), "r"(b[1]));
}
__device__ __forceinline__ void cp16(uint32_t dst, const void* src) {
    asm volatile("cp.async.cg.shared.global [%0], [%1], 16;\n" :: "r"(dst), "l"(src));
}
#define CP_COMMIT() asm volatile("cp.async.commit_group;\n")
#define CP_WAIT0()  asm volatile("cp.async.wait_group 0;\n")
#define CP_WAIT1()  asm volatile("cp.async.wait_group 1;\n")

// fp16 GEMM A-fragment index (m16n8k16), K=2048
__device__ __forceinline__ size_t afragH(int m, int k) {
    return ((size_t)((m >> 4) * KT_A + (k >> 5))) * 512
         + (((k >> 4) & 1) * 256)
         + (((m & 7) * 4 + ((k >> 1) & 3)) * 8)
         + ((((k >> 3) & 1) * 2 + ((m >> 3) & 1)) * 2)
         + (k & 1);
}

// ---------------------------------------------------------------------------
// Fused: LN rows (bid < 4096) + weight prep chunks (bid >= 4096)
// ---------------------------------------------------------------------------
__global__ void __launch_bounds__(256) prep_ln(
    const float* __restrict__ x, const float* __restrict__ g,
    const float* __restrict__ bb, float* __restrict__ y, __half* __restrict__ yp,
    const float* __restrict__ wq, __half* __restrict__ outq,
    const float* __restrict__ wo, __half* __restrict__ outo)
{
    __shared__ float sh[32 * 33];
    const int bid = blockIdx.x;
    const int tx = threadIdx.x;

    if (bid < B_ * S_) {
        // ---- LayerNorm row ----
        const int row = bid;
        const float* xr = x + (size_t)row * H_;
        float s = 0.f, ss = 0.f;
        for (int i = tx; i < H_; i += 256) {
            float t = xr[i];
            s += t; ss += t * t;
        }
        #pragma unroll
        for (int o = 16; o; o >>= 1) {
            s  += __shfl_xor_sync(0xffffffffu, s,  o);
            ss += __shfl_xor_sync(0xffffffffu, ss, o);
        }
        const int w = tx >> 5, l = tx & 31;
        if (l == 0) { sh[w] = s; sh[8 + w] = ss; }
        __syncthreads();
        if (tx == 0) {
            float S = 0.f, SS = 0.f;
            #pragma unroll
            for (int i = 0; i < 8; i++) { S += sh[i]; SS += sh[8 + i]; }
            float mu  = S / (float)H_;
            float var = SS / (float)H_ - mu * mu;
            sh[16] = mu;
            sh[17] = rsqrtf(var + 1e-12f);
        }
        __syncthreads();
        const float mu = sh[16], rstd = sh[17];
        float* yr = y + (size_t)row * H_;
        for (int i = tx; i < H_; i += 256) {
            float v = (xr[i] - mu) * rstd * g[i] + bb[i];
            yr[i] = v;
            yp[afragH(row, i)] = __float2half_rn(v);
        }
    } else {
        // ---- weight prep chunk ----
        const int cid = bid - B_ * S_;
        const int kt = cid & 63;
        int n32 = cid >> 6;
        const float* w;
        __half* out;
        int N;
        if (n32 < 192) { w = wq; out = outq; N = 3 * H_; }
        else           { w = wo; out = outo; N = H_; n32 -= 192; }

        float (*sm)[33] = (float(*)[33])sh;
        const int kl = tx >> 5, nl = tx & 31;
        #pragma unroll
        for (int i = 0; i < 32; i += 8)
            sm[kl + i][nl] = w[(size_t)(kt * 32 + kl + i) * N + n32 * 32 + nl];
        __syncthreads();
        const size_t base = ((size_t)n32 * KT_A + kt) * 1024;
        #pragma unroll
        for (int e = tx; e < 1024; e += 256) {
            const int k = e >> 5, n = e & 31;
            const int off = ((k >> 4) * 512) + (((k >> 3) & 1) * 256)
                          + (((n & 7) * 4 + ((k >> 1) & 3)) * 8)
                          + ((n >> 3) * 2) + (k & 1);
            out[base + off] = __float2half_rn(sm[k][n]);
        }
    }
}

// ---------------------------------------------------------------------------
// FP16 mma.sync GEMM: CTA 64x128, warp tile 32x32, K-slab 64, 3 stages,
// 3 CTAs/SM. EPI 3: Q frags pre-scaled by qscale (= scale*log2e).
// ---------------------------------------------------------------------------
#define STG_HALFS 12288
#define GEMM_SMEM (3 * STG_HALFS * 2)

template<int EPI>
__global__ void __launch_bounds__(256, 3) mma_gemm2(
    const __half* __restrict__ Ap, const __half* __restrict__ Bp,
    float* __restrict__ C,
    __half* __restrict__ Qf, float* __restrict__ Ck, float* __restrict__ Cv,
    __half* __restrict__ Kf, __half* __restrict__ Vf,
    const float* __restrict__ bias, int Ntot, float qscale)
{
    const int m16g0 = blockIdx.y * 4;
    const int n32g0 = blockIdx.x * 4;
    const int rowBase = blockIdx.y * 64;
    const int colBase = blockIdx.x * 128;

    extern __shared__ __half smh[];
    const uint32_t smemU = (uint32_t)__cvta_generic_to_shared(smh);

    const int tx = threadIdx.x;
    const int lane = tx & 31, warp = tx >> 5;
    const int wm = (warp >> 2) * 32;
    const int wn = (warp & 3) * 32;
    const int lr = lane >> 2;
    const int lc = lane & 3;

    auto loadStage = [&](int t, int st) {
        const uint32_t sbase = smemU + st * STG_HALFS * 2;
        #pragma unroll
        for (int i = 0; i < 6; i++) {
            const int idx = tx + i * 256;
            if (idx < 512) {
                const int g = idx >> 7, rem = idx & 127;
                cp16(sbase + idx * 16,
                     Ap + ((size_t)(m16g0 + g) * KT_A + 2 * t) * 512 + rem * 8);
            } else {
                const int j = idx - 512;
                const int nb = j >> 8, rem = j & 255;
                cp16(sbase + idx * 16,
                     Bp + ((size_t)(n32g0 + nb) * KT_A + 2 * t) * 1024 + rem * 8);
            }
        }
    };

    float acc[2][4][4];
    #pragma unroll
    for (int i = 0; i < 2; i++)
        #pragma unroll
        for (int j = 0; j < 4; j++)
            #pragma unroll
            for (int r = 0; r < 4; r++) acc[i][j][r] = 0.f;

    loadStage(0, 0); CP_COMMIT();
    loadStage(1, 1); CP_COMMIT();

    const int T = KT_A / 2;
    for (int t = 0; t < T; t++) {
        const int st = t % 3;
        CP_WAIT1();
        __syncthreads();
        if (t + 2 < T) { loadStage(t + 2, (t + 2) % 3); CP_COMMIT(); }

        const __half* sf = smh + st * STG_HALFS;
        const __half* aB = sf + (warp >> 2) * 2048;
        const __half* bB = sf + 4096 + (warp & 3) * 2048;

        #pragma unroll
        for (int sub = 0; sub < 2; sub++) {
            #pragma unroll
            for (int ks = 0; ks < 2; ks++) {
                uint32_t af[2][4];
                #pragma unroll
                for (int mt = 0; mt < 2; mt++) {
                    uint4 v = *(const uint4*)(aB + mt * 1024 + sub * 512
                                              + ks * 256 + lane * 8);
                    af[mt][0] = v.x; af[mt][1] = v.y; af[mt][2] = v.z; af[mt][3] = v.w;
                }
                uint4 tb0 = *(const uint4*)(bB + sub * 1024 + ks * 512 + lane * 8);
                uint4 tb1 = *(const uint4*)(bB + sub * 1024 + ks * 512 + 256 + lane * 8);
                uint32_t bf[4][2];
                bf[0][0] = tb0.x; bf[0][1] = tb1.x;
                bf[1][0] = tb0.y; bf[1][1] = tb1.y;
                bf[2][0] = tb0.z; bf[2][1] = tb1.z;
                bf[3][0] = tb0.w; bf[3][1] = tb1.w;
                #pragma unroll
                for (int mt = 0; mt < 2; mt++)
                    #pragma unroll
                    for (int nt = 0; nt < 4; nt++)
                        mma_f16(acc[mt][nt], af[mt], bf[nt]);
            }
        }
    }

    if (EPI == 3) {
        const int whichBlk = colBase >> 11;
        const int h = (colBase & 2047) >> 7;
        #pragma unroll
        for (int mt = 0; mt < 2; mt++) {
            #pragma unroll
            for (int nt = 0; nt < 4; nt++) {
                const int gn = colBase + wn + nt * 8 + 2 * lc;
                const int d  = gn & 127;
                const int m0 = rowBase + wm + mt * 16 + lr;
                const int b  = m0 >> 11, s = m0 & 2047;
                float* a = acc[mt][nt];
                const float v00 = a[0] + bias[gn], v01 = a[1] + bias[gn + 1];
                const float v10 = a[2] + bias[gn], v11 = a[3] + bias[gn + 1];
                if (whichBlk == 0) {
                    __half* qp = Qf
                        + (((((size_t)(b * 16 + h) * 16 + (s >> 7)) * 8 + ((s >> 4) & 7)) * 8
                            + (d >> 4)) * 256) + lane * 8 + ((d >> 3) & 1) * 4;
                    *(__half2*)(qp)     = __floats2half2_rn(v00 * qscale, v01 * qscale);
                    *(__half2*)(qp + 2) = __floats2half2_rn(v10 * qscale, v11 * qscale);
                } else {
                    float* base = (whichBlk == 1) ? Ck : Cv;
                    *(float2*)&base[((((size_t)b * 16 + h) << 11) + s) * 128 + d] =
                        make_float2(v00, v01);
                    *(float2*)&base[((((size_t)b * 16 + h) << 11) + s + 8) * 128 + d] =
                        make_float2(v10, v11);
                    if (whichBlk == 1) {
                        __half* kb = Kf + (((size_t)(b * 16 + h) * 32) + (s >> 6)) * 8192
                                   + (d >> 4) * 1024 + lane * 8 + ((d >> 3) & 1) * 2;
                        const int nt0 = (s & 63) >> 3;
                        *(__half2*)(kb + (nt0 >> 1) * 256 + (nt0 & 1) * 4) =
                            __floats2half2_rn(v00, v01);
                        const int nt1 = nt0 + 1;
                        *(__half2*)(kb + (nt1 >> 1) * 256 + (nt1 & 1) * 4) =
                            __floats2half2_rn(v10, v11);
                    } else {
                        const size_t vblk =
                            (((size_t)(b * 16 + h) * 32) + (s >> 6)) * 8192
                            + ((s & 63) >> 4) * 2048 + (d >> 4) * 256;
                        auto vst = [&](int ss, int dd, float val) {
                            const int la = (dd & 7) * 4 + ((ss >> 1) & 3);
                            Vf[vblk + la * 8 + ((dd >> 3) & 1) * 4
                               + ((ss & 15) >> 3) * 2 + (ss & 1)] = __float2half_rn(val);
                        };
                        vst(s, d, v00);     vst(s, d + 1, v01);
                        vst(s + 8, d, v10); vst(s + 8, d + 1, v11);
                    }
                }
            }
        }
        return;
    }

    #pragma unroll
    for (int mt = 0; mt < 2; mt++) {
        #pragma unroll
        for (int nt = 0; nt < 4; nt++) {
            const int gm = rowBase + wm + mt * 16 + lr;
            const int gn = colBase + wn + nt * 8 + 2 * lc;
            float* a = acc[mt][nt];
            #pragma unroll
            for (int r = 0; r < 2; r++)
                *(float2*)&C[(size_t)(gm + r * 8) * Ntot + gn] =
                    make_float2(a[r * 2 + 0], a[r * 2 + 1]);
        }
    }
}

// ---------------------------------------------------------------------------
// FP16 flash attention, 128-key tiles, log2-domain softmax with
// ex2.approx.f16x2 (one MUFU per P pair). Q pre-scaled by scale*log2e.
// ---------------------------------------------------------------------------
#define FLASH_SMEM (4 * 16384 * 2)

__global__ void __launch_bounds__(256, 1) flash_kernel(
    const __half* __restrict__ qf, const __half* __restrict__ kf,
    const __half* __restrict__ vf, const float* __restrict__ mask,
    float* __restrict__ ctx, __half* __restrict__ ctxp)
{
    const int qi = gridDim.x - 1 - blockIdx.x;
    const int rowBase = qi * 128;
    const int bh = blockIdx.y;
    const int b = bh >> 4, h = bh & 15;

    const __half* Kg = kf + (size_t)bh * 32 * 8192;
    const __half* Vg = vf + (size_t)bh * 32 * 8192;
    const float* mrow = mask + (size_t)b * S_;

    extern __shared__ __half smh[];
    const uint32_t smemU = (uint32_t)__cvta_generic_to_shared(smh);

    const int tx = threadIdx.x;
    const int lane = tx & 31, wid = tx >> 5;
    const int lr = lane >> 2, lc = lane & 3;
    const int r0g = rowBase + wid * 16 + lr;
    const int r1g = r0g + 8;

    uint32_t qfr[8][4];
    {
        const __half* Qg = qf + (((size_t)bh * 16 + qi) * 8 + wid) * 2048 + lane * 8;
        #pragma unroll
        for (int ks = 0; ks < 8; ks++) {
            uint4 t = *(const uint4*)(Qg + ks * 256);
            qfr[ks][0] = t.x; qfr[ks][1] = t.y; qfr[ks][2] = t.z; qfr[ks][3] = t.w;
        }
    }

    const int jEnd = qi + 1;
    auto cpKV = [&](int j, int st) {
        const __half* ksrc = Kg + (size_t)j * 16384;
        const __half* vsrc = Vg + (size_t)j * 16384;
        const uint32_t kd = smemU + st * 32768;
        const uint32_t vd = smemU + 65536 + st * 32768;
        #pragma unroll
        for (int i = 0; i < 8; i++) {
            const int i16 = tx + i * 256;
            cp16(kd + i16 * 16, ksrc + i16 * 8);
            cp16(vd + i16 * 16, vsrc + i16 * 8);
        }
    };
    cpKV(0, 0); CP_COMMIT(); CP_WAIT0();
    __syncthreads();

    float oacc[16][4];
    #pragma unroll
    for (int i = 0; i < 16; i++)
        #pragma unroll
        for (int r = 0; r < 4; r++) oacc[i][r] = 0.f;
    float m0 = -1e30f, m1 = -1e30f, l0 = 0.f, l1 = 0.f;

    for (int j = 0; j < jEnd; j++) {
        const int st = j & 1;
        const bool more = (j + 1 < jEnd);
        const bool diag = (j == qi);
        if (more) { cpKV(j + 1, st ^ 1); CP_COMMIT(); }

        // ---- S = Q @ K^T (Q pre-scaled by scale*log2e) ----
        float sacc[16][4];
        #pragma unroll
        for (int nt = 0; nt < 16; nt++)
            #pragma unroll
            for (int r = 0; r < 4; r++) sacc[nt][r] = 0.f;

        const __half* kb = smh + st * 16384;
        #pragma unroll
        for (int ks = 0; ks < 8; ks++) {
            #pragma unroll
            for (int np = 0; np < 8; np++) {
                const __half* p = kb + (np >> 2) * 8192 + ks * 1024
                                + (np & 3) * 256 + lane * 8;
                uint4 t = *(const uint4*)p;
                uint32_t b0[2] = { t.x, t.y };
                uint32_t b1[2] = { t.z, t.w };
                mma_f16(sacc[2 * np],     qfr[ks], b0);
                mma_f16(sacc[2 * np + 1], qfr[ks], b1);
            }
        }

        // ---- mask (log2-domain) + diagonal causal + online softmax ----
        const int keyBase = j * 128;
        float mt0 = -1e30f, mt1 = -1e30f;
        #pragma unroll
        for (int nt = 0; nt < 16; nt++) {
            const int kcol = keyBase + nt * 8 + 2 * lc;
            float2 mk = *(const float2*)&mrow[kcol];
            float s0 = fmaf(mk.x, LOG2E, sacc[nt][0]);
            float s1 = fmaf(mk.y, LOG2E, sacc[nt][1]);
            float s2 = fmaf(mk.x, LOG2E, sacc[nt][2]);
            float s3 = fmaf(mk.y, LOG2E, sacc[nt][3]);
            if (diag) {
                if (kcol     > r0g) s0 = MINF2;
                if (kcol + 1 > r0g) s1 = MINF2;
                if (kcol     > r1g) s2 = MINF2;
                if (kcol + 1 > r1g) s3 = MINF2;
            }
            sacc[nt][0] = s0; sacc[nt][1] = s1; sacc[nt][2] = s2; sacc[nt][3] = s3;
            mt0 = fmaxf(mt0, fmaxf(s0, s1));
            mt1 = fmaxf(mt1, fmaxf(s2, s3));
        }
        mt0 = fmaxf(mt0, __shfl_xor_sync(0xffffffffu, mt0, 1));
        mt0 = fmaxf(mt0, __shfl_xor_sync(0xffffffffu, mt0, 2));
        mt1 = fmaxf(mt1, __shfl_xor_sync(0xffffffffu, mt1, 1));
        mt1 = fmaxf(mt1, __shfl_xor_sync(0xffffffffu, mt1, 2));

        const float mn0 = fmaxf(m0, mt0), mn1 = fmaxf(m1, mt1);
        const float a0 = ex2f(m0 - mn0), a1 = ex2f(m1 - mn1);
        m0 = mn0; m1 = mn1;

        // ---- P = 2^(s-mn) as fp16 pairs; l from the exact fp16 P ----
        uint32_t P[32];
        float ts0 = 0.f, ts1 = 0.f;
        #pragma unroll
        for (int nt = 0; nt < 16; nt++) {
            __half2 d0 = __floats2half2_rn(sacc[nt][0] - mn0, sacc[nt][1] - mn0);
            __half2 d1 = __floats2half2_rn(sacc[nt][2] - mn1, sacc[nt][3] - mn1);
            uint32_t p0, p1;
            asm("ex2.approx.f16x2 %0, %1;" : "=r"(p0) : "r"(h2u(d0)));
            asm("ex2.approx.f16x2 %0, %1;" : "=r"(p1) : "r"(h2u(d1)));
            P[2 * nt]     = p0;
            P[2 * nt + 1] = p1;
            float2 f0 = __half22float2(*(__half2*)&p0);
            float2 f1 = __half22float2(*(__half2*)&p1);
            ts0 += f0.x + f0.y;
            ts1 += f1.x + f1.y;
        }
        ts0 += __shfl_xor_sync(0xffffffffu, ts0, 1);
        ts0 += __shfl_xor_sync(0xffffffffu, ts0, 2);
        ts1 += __shfl_xor_sync(0xffffffffu, ts1, 1);
        ts1 += __shfl_xor_sync(0xffffffffu, ts1, 2);
        l0 = l0 * a0 + ts0;
        l1 = l1 * a1 + ts1;

        #pragma unroll
        for (int nt = 0; nt < 16; nt++) {
            oacc[nt][0] *= a0; oacc[nt][1] *= a0;
            oacc[nt][2] *= a1; oacc[nt][3] *= a1;
        }

        // ---- O += P @ V ----
        const __half* vb = smh + 32768 + st * 16384;
        #pragma unroll
        for (int ks = 0; ks < 8; ks++) {
            const uint32_t* af = &P[4 * ks];
            const __half* vt = vb + (ks >> 2) * 8192 + (ks & 3) * 2048;
            #pragma unroll
            for (int np = 0; np < 8; np++) {
                uint4 t = *(const uint4*)(vt + np * 256 + lane * 8);
                uint32_t b0[2] = { t.x, t.y };
                uint32_t b1[2] = { t.z, t.w };
                mma_f16(oacc[2 * np],     af, b0);
                mma_f16(oacc[2 * np + 1], af, b1);
            }
        }

        if (more) { CP_WAIT0(); __syncthreads(); }
    }

    const float inv0 = 1.0f / l0;
    const float inv1 = 1.0f / l1;
    const size_t o0 = ((size_t)b * S_ + r0g) * H_ + h * 128 + 2 * lc;
    const size_t o1 = ((size_t)b * S_ + r1g) * H_ + h * 128 + 2 * lc;
    const int mg = b * S_ + r0g;
    #pragma unroll
    for (int nt = 0; nt < 16; nt++) {
        float v0 = oacc[nt][0] * inv0, v1 = oacc[nt][1] * inv0;
        float v2 = oacc[nt][2] * inv1, v3 = oacc[nt][3] * inv1;
        *(float2*)(ctx + o0 + nt * 8) = make_float2(v0, v1);
        *(float2*)(ctx + o1 + nt * 8) = make_float2(v2, v3);
        const int k0 = h * 128 + nt * 8 + 2 * lc;
        __half2 h01 = __floats2half2_rn(v0, v1);
        __half2 h23 = __floats2half2_rn(v2, v3);
        uint2 u = make_uint2(h2u(h01), h2u(h23));
        *(uint2*)&ctxp[afragH(mg, k0)] = u;
    }
}

// ---------------------------------------------------------------------------
extern "C" void kernel_launch(void* const* d_in, const int* in_sizes, int n_in,
                              void* d_out, int out_size)
{
    const float* x    = (const float*)d_in[0];
    const float* mask = (const float*)d_in[1];
    const float* qkvw = (const float*)d_in[2];
    const float* qkvb = (const float*)d_in[3];
    const float* ow   = (const float*)d_in[4];
    const float* nw   = (const float*)d_in[5];
    const float* nb   = (const float*)d_in[6];

    float* out     = (float*)d_out;
    float* out_o   = out;
    float* out_k   = out + 1 * BSH;
    float* out_v   = out + 2 * BSH;
    float* out_ctx = out + 3 * BSH;
    float* out_ln  = out + 4 * BSH;

    __half *qfr, *kfr, *vfr, *lnp, *ctxp, *qkvwP, *owP;
    cudaGetSymbolAddress((void**)&qfr,   g_qfr);
    cudaGetSymbolAddress((void**)&kfr,   g_kfr);
    cudaGetSymbolAddress((void**)&vfr,   g_vfr);
    cudaGetSymbolAddress((void**)&lnp,   g_lnp);
    cudaGetSymbolAddress((void**)&ctxp,  g_ctxp);
    cudaGetSymbolAddress((void**)&qkvwP, g_qkvwP);
    cudaGetSymbolAddress((void**)&owP,   g_owP);

    cudaFuncSetAttribute(mma_gemm2<3>, cudaFuncAttributeMaxDynamicSharedMemorySize, GEMM_SMEM);
    cudaFuncSetAttribute(mma_gemm2<0>, cudaFuncAttributeMaxDynamicSharedMemorySize, GEMM_SMEM);
    cudaFuncSetAttribute(flash_kernel, cudaFuncAttributeMaxDynamicSharedMemorySize, FLASH_SMEM);

    const float qscale = (1.0f / sqrtf((float)DH)) * LOG2E;

    // 0+1. Fused weight prep + LayerNorm
    prep_ln<<<B_ * S_ + KT_A * 256, 256>>>(
        x, nw, nb, out_ln, lnp, qkvw, qkvwP, ow, owP);

    // 2. QKV GEMM + scatter
    mma_gemm2<3><<<dim3(48, 64), 256, GEMM_SMEM>>>(
        lnp, qkvwP, nullptr, qfr, out_k, out_v, kfr, vfr, qkvb, 3 * H_, qscale);

    // 3. Flash attention
    flash_kernel<<<dim3(16, BH), 256, FLASH_SMEM>>>(
        qfr, kfr, vfr, mask, out_ctx, ctxp);

    // 4. Output projection
    mma_gemm2<0><<<dim3(16, 64), 256, GEMM_SMEM>>>(
        ctxp, owP, out_o, nullptr, nullptr, nullptr, nullptr, nullptr, nullptr, H_, 1.0f);
}